// round 14
// baseline (speedup 1.0000x reference)
#include <cuda_runtime.h>
#include <cuda_bf16.h>
#include <math.h>
#include <stdint.h>

// ---------------- problem constants ----------------
#define NNODES   10000
#define F_IN     384
#define HID      256
#define OUT_D    128
#define ATT_H    64
#define EDGES_MAX 320000

#define SCAN_BLOCKS 40
#define SCAN_TPB    256   // 40*256 = 10240 >= NNODES

// ---------------- scratch (device globals; no allocation allowed) ----------------
__device__ float           g_h  [NNODES * HID];     // relu(x W1^T + b1), 256-wide
__device__ float           g_z  [NNODES * OUT_D];   // h @ W2^T (pre-bias/relu), 128-wide
__device__ float           g_z2 [NNODES * OUT_D];
__device__ __nv_bfloat16   g_zb [NNODES * OUT_D];   // bf16 shadows for neighbor reads
__device__ __nv_bfloat16   g_zb2[NNODES * OUT_D];
__device__ float g_inv[NNODES];
__device__ int   g_cnt[NNODES];          // zero-init; re-zeroed by scan3 each launch
__device__ int   g_off[NNODES + 1];
__device__ int   g_cur[NNODES];
__device__ int   g_bsum[SCAN_BLOCKS];
__device__ int   g_bofs[SCAN_BLOCKS];
__device__ int   g_srcs[EDGES_MAX];
__device__ float g_WaT[OUT_D * ATT_H];   // Wa1 transposed

// ---------------- count in-degree, 4 edges/thread ----------------
__global__ void count_kernel(const int* __restrict__ tgt, int* __restrict__ cnt, int E) {
    int i = (blockIdx.x * blockDim.x + threadIdx.x) * 4;
    if (i + 4 <= E) {
        int t0 = tgt[i], t1 = tgt[i + 1], t2 = tgt[i + 2], t3 = tgt[i + 3];
        atomicAdd(&cnt[t0], 1);
        atomicAdd(&cnt[t1], 1);
        atomicAdd(&cnt[t2], 1);
        atomicAdd(&cnt[t3], 1);
    } else {
        for (; i < E; i++) atomicAdd(&cnt[tgt[i]], 1);
    }
}

// ---------------- scan phase 1 ----------------
__global__ __launch_bounds__(SCAN_TPB) void scan1_kernel(
    const int* __restrict__ cnt, int* __restrict__ bsum)
{
    __shared__ int wsum[SCAN_TPB / 32];
    int idx = blockIdx.x * SCAN_TPB + threadIdx.x;
    int v = (idx < NNODES) ? cnt[idx] : 0;
    int lane = threadIdx.x & 31;
    int warp = threadIdx.x >> 5;
#pragma unroll
    for (int d = 16; d; d >>= 1) v += __shfl_xor_sync(0xffffffffu, v, d);
    if (lane == 0) wsum[warp] = v;
    __syncthreads();
    if (threadIdx.x == 0) {
        int s = 0;
#pragma unroll
        for (int w = 0; w < SCAN_TPB / 32; w++) s += wsum[w];
        bsum[blockIdx.x] = s;
    }
}

// ---------------- scan phase 2 ----------------
__global__ void scan2_kernel(const int* __restrict__ bsum, int* __restrict__ bofs,
                             int* __restrict__ off)
{
    int lane = threadIdx.x;
    int v = (lane < SCAN_BLOCKS) ? bsum[lane] : 0;
    int lane32 = lane & 31;
    int half = lane >> 5;
    int s = v;
#pragma unroll
    for (int d = 1; d < 32; d <<= 1) {
        int t = __shfl_up_sync(0xffffffffu, s, d);
        if (lane32 >= d) s += t;
    }
    __shared__ int w0tot;
    if (lane == 31) w0tot = s;
    __syncthreads();
    int incl = s + (half ? w0tot : 0);
    if (lane < SCAN_BLOCKS) bofs[lane] = incl - v;
    if (lane == SCAN_BLOCKS - 1) off[NNODES] = incl;
}

// ---------------- scan phase 3 ----------------
__global__ __launch_bounds__(SCAN_TPB) void scan3_kernel(
    int* __restrict__ cnt, const int* __restrict__ bofs,
    int* __restrict__ off, int* __restrict__ cur, float* __restrict__ inv)
{
    __shared__ int wsum[SCAN_TPB / 32];
    int idx = blockIdx.x * SCAN_TPB + threadIdx.x;
    int lane = threadIdx.x & 31;
    int warp = threadIdx.x >> 5;
    int v = (idx < NNODES) ? cnt[idx] : 0;

    int s = v;
#pragma unroll
    for (int d = 1; d < 32; d <<= 1) {
        int t = __shfl_up_sync(0xffffffffu, s, d);
        if (lane >= d) s += t;
    }
    if (lane == 31) wsum[warp] = s;
    __syncthreads();
    if (warp == 0) {
        int ws = (lane < SCAN_TPB / 32) ? wsum[lane] : 0;
#pragma unroll
        for (int d = 1; d < SCAN_TPB / 32; d <<= 1) {
            int t = __shfl_up_sync(0xffffffffu, ws, d);
            if (lane >= d) ws += t;
        }
        if (lane < SCAN_TPB / 32) wsum[lane] = ws;
    }
    __syncthreads();
    int excl = s - v + (warp ? wsum[warp - 1] : 0) + bofs[blockIdx.x];
    if (idx < NNODES) {
        off[idx] = excl;
        cur[idx] = excl;
        inv[idx] = 1.0f / ((float)v + 1.0f);
        cnt[idx] = 0;
    }
}

// ---------------- fill CSR buckets ----------------
__global__ void fill_kernel(const int* __restrict__ src, const int* __restrict__ tgt,
                            int* __restrict__ cur, int* __restrict__ srcs, int E)
{
    int i = (blockIdx.x * blockDim.x + threadIdx.x) * 4;
    if (i + 4 <= E) {
        int t0 = tgt[i], t1 = tgt[i + 1], t2 = tgt[i + 2], t3 = tgt[i + 3];
        int s0 = src[i], s1 = src[i + 1], s2 = src[i + 2], s3 = src[i + 3];
        int p0 = atomicAdd(&cur[t0], 1);
        int p1 = atomicAdd(&cur[t1], 1);
        int p2 = atomicAdd(&cur[t2], 1);
        int p3 = atomicAdd(&cur[t3], 1);
        srcs[p0] = s0;
        srcs[p1] = s1;
        srcs[p2] = s2;
        srcs[p3] = s3;
    } else {
        for (; i < E; i++) {
            int p = atomicAdd(&cur[tgt[i]], 1);
            srcs[p] = src[i];
        }
    }
}

// ---------------- 128-wide fused gather + combine (unchanged from 96.3us state) ----------------
__device__ __forceinline__ void acc_bf16x4(float4& acc, uint2 p) {
    __nv_bfloat162 lo = *reinterpret_cast<__nv_bfloat162*>(&p.x);
    __nv_bfloat162 hi = *reinterpret_cast<__nv_bfloat162*>(&p.y);
    float2 f0 = __bfloat1622float2(lo);
    float2 f1 = __bfloat1622float2(hi);
    acc.x += f0.x; acc.y += f0.y; acc.z += f1.x; acc.w += f1.y;
}

__global__ __launch_bounds__(256) void gather_combine128_kernel(
    const float* __restrict__ zin, const __nv_bfloat16* __restrict__ zbin,
    float* __restrict__ zout, __nv_bfloat16* __restrict__ zbout,
    const float* __restrict__ b2,        // non-null => final pass: +bias, relu, no shadow
    const int* __restrict__ off, const int* __restrict__ srcs,
    const float* __restrict__ inv)
{
    int node = blockIdx.x * 8 + (threadIdx.x >> 5);
    int c = (threadIdx.x & 31) << 2;

    int beg = 0, end = 0;
    if (node < NNODES) {
        beg = __ldg(off + node);
        end = __ldg(off + node + 1);
    }

    cudaGridDependencySynchronize();

    if (node >= NNODES) return;

    float4 acc = make_float4(0.f, 0.f, 0.f, 0.f);
    int i = beg;
    for (; i + 4 <= end; i += 4) {
        int s0 = __ldg(srcs + i);
        int s1 = __ldg(srcs + i + 1);
        int s2 = __ldg(srcs + i + 2);
        int s3 = __ldg(srcs + i + 3);
        uint2 p0 = *reinterpret_cast<const uint2*>(zbin + (size_t)s0 * OUT_D + c);
        uint2 p1 = *reinterpret_cast<const uint2*>(zbin + (size_t)s1 * OUT_D + c);
        uint2 p2 = *reinterpret_cast<const uint2*>(zbin + (size_t)s2 * OUT_D + c);
        uint2 p3 = *reinterpret_cast<const uint2*>(zbin + (size_t)s3 * OUT_D + c);
        acc_bf16x4(acc, p0);
        acc_bf16x4(acc, p1);
        acc_bf16x4(acc, p2);
        acc_bf16x4(acc, p3);
    }
    for (; i < end; i++) {
        int s0 = __ldg(srcs + i);
        uint2 p0 = *reinterpret_cast<const uint2*>(zbin + (size_t)s0 * OUT_D + c);
        acc_bf16x4(acc, p0);
    }

    float sc = 0.3f * inv[node];
    float4 zv = *reinterpret_cast<const float4*>(zin + (size_t)node * OUT_D + c);
    zv.x = 0.7f * zv.x + sc * acc.x;
    zv.y = 0.7f * zv.y + sc * acc.y;
    zv.z = 0.7f * zv.z + sc * acc.z;
    zv.w = 0.7f * zv.w + sc * acc.w;

    if (b2) {
        float4 bv = *reinterpret_cast<const float4*>(b2 + c);
        zv.x = fmaxf(zv.x + bv.x, 0.f);
        zv.y = fmaxf(zv.y + bv.y, 0.f);
        zv.z = fmaxf(zv.z + bv.z, 0.f);
        zv.w = fmaxf(zv.w + bv.w, 0.f);
        *reinterpret_cast<float4*>(zout + (size_t)node * OUT_D + c) = zv;
    } else {
        *reinterpret_cast<float4*>(zout + (size_t)node * OUT_D + c) = zv;
        uint2 pk;
        __nv_bfloat162 lo = __floats2bfloat162_rn(zv.x, zv.y);
        __nv_bfloat162 hi = __floats2bfloat162_rn(zv.z, zv.w);
        pk.x = *reinterpret_cast<uint32_t*>(&lo);
        pk.y = *reinterpret_cast<uint32_t*>(&hi);
        *reinterpret_cast<uint2*>(zbout + (size_t)node * OUT_D + c) = pk;
    }

    cudaTriggerProgrammaticLaunchCompletion();
}

// ---------------- tf32 tensor-core GEMM: 2-stage double-buffered smem, PDL-aware ----------------
#define GBM 128
#define GBN 64
#define GBK 32
#define SKA 36
// dynamic smem: two stages of (A: GBM x SKA) + (B: GBN x SKA) uint32
#define SMEM_GEMM ((2 * (GBM + GBN) * SKA) * 4)

__device__ __forceinline__ uint32_t f2tf32(float x) {
    uint32_t r;
    asm("cvt.rna.tf32.f32 %0, %1;" : "=r"(r) : "f"(x));
    return r;
}

__device__ __forceinline__ void mma_tf32(float* c, const uint32_t* a, const uint32_t* b) {
    asm volatile(
        "mma.sync.aligned.m16n8k8.row.col.f32.tf32.tf32.f32 "
        "{%0,%1,%2,%3}, {%4,%5,%6,%7}, {%8,%9}, {%0,%1,%2,%3};"
        : "+f"(c[0]), "+f"(c[1]), "+f"(c[2]), "+f"(c[3])
        : "r"(a[0]), "r"(a[1]), "r"(a[2]), "r"(a[3]), "r"(b[0]), "r"(b[1]));
}

__global__ __launch_bounds__(256) void gemm_tf32_kernel(
    const float* __restrict__ A, const float* __restrict__ B,
    const float* __restrict__ bias,          // nullable
    float* __restrict__ C,
    __nv_bfloat16* __restrict__ Cb,          // nullable
    int M, int N, int K, int do_relu)
{
    extern __shared__ uint32_t sm[];
    // layout: A0 | A1 | B0 | B1
    uint32_t* Abuf[2] = { sm, sm + GBM * SKA };
    uint32_t* Bbuf[2] = { sm + 2 * GBM * SKA, sm + 2 * GBM * SKA + GBN * SKA };

    const int tid  = threadIdx.x;
    const int lane = tid & 31;
    const int warp = tid >> 5;
    const int wm = warp >> 1;
    const int wn = warp & 1;
    const int g   = lane >> 2;
    const int tig = lane & 3;
    const int m0 = blockIdx.y * GBM;
    const int n0 = blockIdx.x * GBN;

    const int ar = tid >> 3;            // row within tile (plus +32*it)
    const int ac4 = (tid & 7) << 2;     // k-offset (float4 granular)

    cudaGridDependencySynchronize();

    float acc[2][4][4];
#pragma unroll
    for (int mm = 0; mm < 2; mm++)
#pragma unroll
        for (int nn = 0; nn < 4; nn++)
#pragma unroll
            for (int q = 0; q < 4; q++) acc[mm][nn][q] = 0.0f;

    float4 ra[4], rb[2];
#pragma unroll
    for (int it = 0; it < 4; it++) {
        int r = ar + it * 32;
        int gm = m0 + r;
        ra[it] = (gm < M) ? *reinterpret_cast<const float4*>(A + (size_t)gm * K + ac4)
                          : make_float4(0.f, 0.f, 0.f, 0.f);
    }
#pragma unroll
    for (int it = 0; it < 2; it++) {
        int r = ar + it * 32;
        rb[it] = *reinterpret_cast<const float4*>(B + (size_t)(n0 + r) * K + ac4);
    }

    const int NIT = K / GBK;
    for (int itk = 0; itk < NIT; itk++) {
        const int buf = itk & 1;
        uint32_t* As = Abuf[buf];
        uint32_t* Bs = Bbuf[buf];

        // store current regs -> smem stage (packed STS.128)
#pragma unroll
        for (int it = 0; it < 4; it++) {
            int r = ar + it * 32;
            uint4 pk;
            pk.x = f2tf32(ra[it].x);
            pk.y = f2tf32(ra[it].y);
            pk.z = f2tf32(ra[it].z);
            pk.w = f2tf32(ra[it].w);
            *reinterpret_cast<uint4*>(As + r * SKA + ac4) = pk;
        }
#pragma unroll
        for (int it = 0; it < 2; it++) {
            int r = ar + it * 32;
            uint4 pk;
            pk.x = f2tf32(rb[it].x);
            pk.y = f2tf32(rb[it].y);
            pk.z = f2tf32(rb[it].z);
            pk.w = f2tf32(rb[it].w);
            *reinterpret_cast<uint4*>(Bs + r * SKA + ac4) = pk;
        }

        // prefetch next tile (in flight across the barrier + compute)
        int kn = (itk + 1) * GBK;
        if (kn < K) {
#pragma unroll
            for (int it = 0; it < 4; it++) {
                int r = ar + it * 32;
                int gm = m0 + r;
                ra[it] = (gm < M) ? *reinterpret_cast<const float4*>(A + (size_t)gm * K + kn + ac4)
                                  : make_float4(0.f, 0.f, 0.f, 0.f);
            }
#pragma unroll
            for (int it = 0; it < 2; it++) {
                int r = ar + it * 32;
                rb[it] = *reinterpret_cast<const float4*>(B + (size_t)(n0 + r) * K + kn + ac4);
            }
        }

        __syncthreads();   // single barrier per k-tile: stage `buf` visible everywhere

#pragma unroll
        for (int kk = 0; kk < GBK; kk += 8) {
            uint32_t af[2][4];
#pragma unroll
            for (int mm = 0; mm < 2; mm++) {
                int row = wm * 32 + mm * 16 + g;
                af[mm][0] = As[row * SKA + kk + tig];
                af[mm][1] = As[(row + 8) * SKA + kk + tig];
                af[mm][2] = As[row * SKA + kk + tig + 4];
                af[mm][3] = As[(row + 8) * SKA + kk + tig + 4];
            }
            uint32_t bf[4][2];
#pragma unroll
            for (int nn = 0; nn < 4; nn++) {
                int col = wn * 32 + nn * 8 + g;
                bf[nn][0] = Bs[col * SKA + kk + tig];
                bf[nn][1] = Bs[col * SKA + kk + tig + 4];
            }
#pragma unroll
            for (int mm = 0; mm < 2; mm++)
#pragma unroll
                for (int nn = 0; nn < 4; nn++)
                    mma_tf32(acc[mm][nn], af[mm], bf[nn]);
        }
        // no trailing barrier: next iteration writes the OTHER stage; the next
        // iteration's mid-loop barrier orders stage reuse two iterations apart.
    }

#pragma unroll
    for (int mm = 0; mm < 2; mm++) {
        int r0 = m0 + wm * 32 + mm * 16 + g;
#pragma unroll
        for (int nn = 0; nn < 4; nn++) {
            int col = n0 + wn * 32 + nn * 8 + tig * 2;
            float b0 = bias ? bias[col]     : 0.f;
            float b1 = bias ? bias[col + 1] : 0.f;
#pragma unroll
            for (int half = 0; half < 2; half++) {
                int r = r0 + half * 8;
                if (r >= M) continue;
                float v0 = acc[mm][nn][half * 2 + 0] + b0;
                float v1 = acc[mm][nn][half * 2 + 1] + b1;
                if (do_relu) { v0 = fmaxf(v0, 0.f); v1 = fmaxf(v1, 0.f); }
                C[(size_t)r * N + col]     = v0;
                C[(size_t)r * N + col + 1] = v1;
                if (Cb) {
                    __nv_bfloat162 p = __floats2bfloat162_rn(v0, v1);
                    *reinterpret_cast<uint32_t*>(Cb + (size_t)r * N + col) =
                        *reinterpret_cast<uint32_t*>(&p);
                }
            }
        }
    }

    cudaTriggerProgrammaticLaunchCompletion();
}

// ---------------- transpose Wa1 (64x128) -> WaT (128x64) ----------------
__global__ void transpose_wa1_kernel(const float* __restrict__ Wa1, float* __restrict__ WaT) {
    int idx = blockIdx.x * blockDim.x + threadIdx.x;
    if (idx >= OUT_D * ATT_H) return;
    int k = idx / ATT_H;
    int j = idx % ATT_H;
    WaT[idx] = Wa1[j * OUT_D + k];
}

// ---------------- attention: warp per node (lean, PDL consumer) ----------------
__global__ __launch_bounds__(256) void attention_kernel(
    const float* __restrict__ out, const float* __restrict__ WaT,
    const float* __restrict__ ba1, const float* __restrict__ Wa2,
    const float* __restrict__ ba2, float* __restrict__ att, int N)
{
    int warp = (blockIdx.x * blockDim.x + threadIdx.x) >> 5;
    int lane = threadIdx.x & 31;

    float acc0 = ba1[lane];
    float acc1 = ba1[lane + 32];
    float w2a = Wa2[lane];
    float w2b = Wa2[lane + 32];
    float bb2 = ba2[0];

    cudaGridDependencySynchronize();

    if (warp >= N) return;
    const float* o = out + (size_t)warp * OUT_D;
#pragma unroll 4
    for (int k = 0; k < OUT_D; k++) {
        float ov = __ldg(o + k);
        acc0 = fmaf(WaT[k * ATT_H + lane],      ov, acc0);
        acc1 = fmaf(WaT[k * ATT_H + lane + 32], ov, acc1);
    }
    acc0 = fmaxf(acc0, 0.0f) * w2a;
    acc1 = fmaxf(acc1, 0.0f) * w2b;
    float s = acc0 + acc1;
#pragma unroll
    for (int off = 16; off; off >>= 1) s += __shfl_xor_sync(0xffffffffu, s, off);
    if (lane == 0) att[warp] = 1.0f / (1.0f + expf(-(s + bb2)));
}

// ---------------- PDL launch helper ----------------
template <typename F, typename... Args>
static inline void launch_pdl(F kern, dim3 grid, dim3 block, size_t smem, Args... args) {
    cudaLaunchConfig_t cfg = {};
    cfg.gridDim = grid;
    cfg.blockDim = block;
    cfg.dynamicSmemBytes = smem;
    cfg.stream = 0;
    cudaLaunchAttribute attr[1];
    attr[0].id = cudaLaunchAttributeProgrammaticStreamSerialization;
    attr[0].val.programmaticStreamSerializationAllowed = 1;
    cfg.attrs = attr;
    cfg.numAttrs = 1;
    cudaLaunchKernelEx(&cfg, kern, args...);
}

// ---------------- launch ----------------
extern "C" void kernel_launch(void* const* d_in, const int* in_sizes, int n_in,
                              void* d_out, int out_size)
{
    const float* x    = (const float*)d_in[0];
    const int*   ei   = (const int*)d_in[1];     // (2, E) int32: [src | tgt]
    const float* W1   = (const float*)d_in[2];
    const float* b1   = (const float*)d_in[3];
    const float* W2   = (const float*)d_in[4];
    const float* b2   = (const float*)d_in[5];
    const float* Wa1  = (const float*)d_in[6];
    const float* ba1  = (const float*)d_in[7];
    const float* Wa2  = (const float*)d_in[8];
    const float* ba2  = (const float*)d_in[9];

    const int E = in_sizes[1] / 2;
    const int* src = ei;
    const int* tgt = ei + E;

    float* out_ptr = (float*)d_out;                        // (N, 128)
    float* att_ptr = out_ptr + (size_t)NNODES * OUT_D;     // (N, 1)

    float*         h_p;    cudaGetSymbolAddress((void**)&h_p,    g_h);
    float*         z_p;    cudaGetSymbolAddress((void**)&z_p,    g_z);
    float*         z2_p;   cudaGetSymbolAddress((void**)&z2_p,   g_z2);
    __nv_bfloat16* zb_p;   cudaGetSymbolAddress((void**)&zb_p,   g_zb);
    __nv_bfloat16* zb2_p;  cudaGetSymbolAddress((void**)&zb2_p,  g_zb2);
    float*         inv_p;  cudaGetSymbolAddress((void**)&inv_p,  g_inv);
    int*           cnt_p;  cudaGetSymbolAddress((void**)&cnt_p,  g_cnt);
    int*           off_p;  cudaGetSymbolAddress((void**)&off_p,  g_off);
    int*           cur_p;  cudaGetSymbolAddress((void**)&cur_p,  g_cur);
    int*           bsum_p; cudaGetSymbolAddress((void**)&bsum_p, g_bsum);
    int*           bofs_p; cudaGetSymbolAddress((void**)&bofs_p, g_bofs);
    int*           srcs_p; cudaGetSymbolAddress((void**)&srcs_p, g_srcs);
    float*         wat_p;  cudaGetSymbolAddress((void**)&wat_p,  g_WaT);

    // allow 55KB dynamic smem on the GEMM (host-side attr; idempotent)
    cudaFuncSetAttribute(gemm_tf32_kernel,
                         cudaFuncAttributeMaxDynamicSharedMemorySize, SMEM_GEMM);

    // --- fork side stream: CSR build + Wa1 transpose (hides under GEMMs) ---
    cudaStream_t side;
    cudaStreamCreateWithFlags(&side, cudaStreamNonBlocking);
    cudaEvent_t ev_fork, ev_csr;
    cudaEventCreateWithFlags(&ev_fork, cudaEventDisableTiming);
    cudaEventCreateWithFlags(&ev_csr,  cudaEventDisableTiming);

    cudaEventRecord(ev_fork, 0);
    cudaStreamWaitEvent(side, ev_fork, 0);

    // side branch part 1 (5 launches)
    transpose_wa1_kernel<<<(OUT_D * ATT_H + 255) / 256, 256, 0, side>>>(Wa1, wat_p);
    count_kernel<<<(E / 4 + 255) / 256, 256, 0, side>>>(tgt, cnt_p, E);
    scan1_kernel<<<SCAN_BLOCKS, SCAN_TPB, 0, side>>>(cnt_p, bsum_p);
    scan2_kernel<<<1, 64, 0, side>>>(bsum_p, bofs_p, off_p);
    scan3_kernel<<<SCAN_BLOCKS, SCAN_TPB, 0, side>>>(cnt_p, bofs_p, off_p, cur_p, inv_p);

    // main: h = relu(x @ W1^T + b1) — launched 6th so ncu (-s 5 -c 1) captures it
    {
        dim3 grid(HID / GBN, (NNODES + GBM - 1) / GBM);
        gemm_tf32_kernel<<<grid, 256, SMEM_GEMM>>>(x, W1, b1, h_p, (__nv_bfloat16*)nullptr,
                                                   NNODES, HID, F_IN, 1);
    }

    // side branch part 2 (fill depends only on scan3 — side-stream order preserved)
    fill_kernel<<<(E / 4 + 255) / 256, 256, 0, side>>>(src, tgt, cur_p, srcs_p, E);
    cudaEventRecord(ev_csr, side);

    // main: z = h @ W2^T  (PDL on gemm1)
    {
        dim3 grid(OUT_D / GBN, (NNODES + GBM - 1) / GBM);
        launch_pdl(gemm_tf32_kernel, grid, dim3(256), (size_t)SMEM_GEMM,
                   h_p, (const float*)W2, (const float*)nullptr, z_p, zb_p,
                   NNODES, OUT_D, HID, 0);
    }

    cudaStreamWaitEvent(0, ev_csr, 0);

    // propagation in z-space (PDL chain): z2 = P z ; out = relu(P z2 + b2)
    {
        int gblocks = (NNODES + 7) / 8;
        launch_pdl(gather_combine128_kernel, dim3(gblocks), dim3(256), (size_t)0,
                   (const float*)z_p, (const __nv_bfloat16*)zb_p, z2_p, zb2_p,
                   (const float*)nullptr,
                   (const int*)off_p, (const int*)srcs_p, (const float*)inv_p);
        launch_pdl(gather_combine128_kernel, dim3(gblocks), dim3(256), (size_t)0,
                   (const float*)z2_p, (const __nv_bfloat16*)zb2_p, out_ptr,
                   (__nv_bfloat16*)nullptr, (const float*)b2,
                   (const int*)off_p, (const int*)srcs_p, (const float*)inv_p);
    }

    // attention (PDL on gather pass 2)
    launch_pdl(attention_kernel, dim3((NNODES * 32 + 255) / 256), dim3(256), (size_t)0,
               (const float*)out_ptr, (const float*)wat_p, ba1, Wa2, ba2,
               att_ptr, NNODES);

    cudaEventDestroy(ev_fork);
    cudaEventDestroy(ev_csr);
    cudaStreamDestroy(side);
}

// round 15
// speedup vs baseline: 1.1068x; 1.1068x over previous
#include <cuda_runtime.h>
#include <cuda_bf16.h>
#include <math.h>
#include <stdint.h>

// ---------------- problem constants ----------------
#define NNODES   10000
#define F_IN     384
#define HID      256
#define OUT_D    128
#define ATT_H    64
#define EDGES_MAX 320000

#define SCAN_BLOCKS 40
#define SCAN_TPB    256   // 40*256 = 10240 >= NNODES

// ---------------- scratch (device globals; no allocation allowed) ----------------
__device__ float           g_h  [NNODES * HID];     // relu(x W1^T + b1), 256-wide
__device__ float           g_z  [NNODES * OUT_D];   // h @ W2^T (pre-bias/relu), 128-wide
__device__ float           g_z2 [NNODES * OUT_D];
__device__ __nv_bfloat16   g_zb [NNODES * OUT_D];   // bf16 shadows for neighbor reads
__device__ __nv_bfloat16   g_zb2[NNODES * OUT_D];
__device__ float g_inv[NNODES];
__device__ int   g_cnt[NNODES];          // zero-init; re-zeroed by scan3 each launch
__device__ int   g_off[NNODES + 1];
__device__ int   g_cur[NNODES];
__device__ int   g_bsum[SCAN_BLOCKS];
__device__ int   g_bofs[SCAN_BLOCKS];
__device__ int   g_srcs[EDGES_MAX];
__device__ float g_WaT[OUT_D * ATT_H];   // Wa1 transposed

// ---------------- count in-degree, 4 edges/thread ----------------
__global__ void count_kernel(const int* __restrict__ tgt, int* __restrict__ cnt, int E) {
    int i = (blockIdx.x * blockDim.x + threadIdx.x) * 4;
    if (i + 4 <= E) {
        int t0 = tgt[i], t1 = tgt[i + 1], t2 = tgt[i + 2], t3 = tgt[i + 3];
        atomicAdd(&cnt[t0], 1);
        atomicAdd(&cnt[t1], 1);
        atomicAdd(&cnt[t2], 1);
        atomicAdd(&cnt[t3], 1);
    } else {
        for (; i < E; i++) atomicAdd(&cnt[tgt[i]], 1);
    }
}

// ---------------- scan phase 1 ----------------
__global__ __launch_bounds__(SCAN_TPB) void scan1_kernel(
    const int* __restrict__ cnt, int* __restrict__ bsum)
{
    __shared__ int wsum[SCAN_TPB / 32];
    int idx = blockIdx.x * SCAN_TPB + threadIdx.x;
    int v = (idx < NNODES) ? cnt[idx] : 0;
    int lane = threadIdx.x & 31;
    int warp = threadIdx.x >> 5;
#pragma unroll
    for (int d = 16; d; d >>= 1) v += __shfl_xor_sync(0xffffffffu, v, d);
    if (lane == 0) wsum[warp] = v;
    __syncthreads();
    if (threadIdx.x == 0) {
        int s = 0;
#pragma unroll
        for (int w = 0; w < SCAN_TPB / 32; w++) s += wsum[w];
        bsum[blockIdx.x] = s;
    }
}

// ---------------- scan phase 2 ----------------
__global__ void scan2_kernel(const int* __restrict__ bsum, int* __restrict__ bofs,
                             int* __restrict__ off)
{
    int lane = threadIdx.x;
    int v = (lane < SCAN_BLOCKS) ? bsum[lane] : 0;
    int lane32 = lane & 31;
    int half = lane >> 5;
    int s = v;
#pragma unroll
    for (int d = 1; d < 32; d <<= 1) {
        int t = __shfl_up_sync(0xffffffffu, s, d);
        if (lane32 >= d) s += t;
    }
    __shared__ int w0tot;
    if (lane == 31) w0tot = s;
    __syncthreads();
    int incl = s + (half ? w0tot : 0);
    if (lane < SCAN_BLOCKS) bofs[lane] = incl - v;
    if (lane == SCAN_BLOCKS - 1) off[NNODES] = incl;
}

// ---------------- scan phase 3 ----------------
__global__ __launch_bounds__(SCAN_TPB) void scan3_kernel(
    int* __restrict__ cnt, const int* __restrict__ bofs,
    int* __restrict__ off, int* __restrict__ cur, float* __restrict__ inv)
{
    __shared__ int wsum[SCAN_TPB / 32];
    int idx = blockIdx.x * SCAN_TPB + threadIdx.x;
    int lane = threadIdx.x & 31;
    int warp = threadIdx.x >> 5;
    int v = (idx < NNODES) ? cnt[idx] : 0;

    int s = v;
#pragma unroll
    for (int d = 1; d < 32; d <<= 1) {
        int t = __shfl_up_sync(0xffffffffu, s, d);
        if (lane >= d) s += t;
    }
    if (lane == 31) wsum[warp] = s;
    __syncthreads();
    if (warp == 0) {
        int ws = (lane < SCAN_TPB / 32) ? wsum[lane] : 0;
#pragma unroll
        for (int d = 1; d < SCAN_TPB / 32; d <<= 1) {
            int t = __shfl_up_sync(0xffffffffu, ws, d);
            if (lane >= d) ws += t;
        }
        if (lane < SCAN_TPB / 32) wsum[lane] = ws;
    }
    __syncthreads();
    int excl = s - v + (warp ? wsum[warp - 1] : 0) + bofs[blockIdx.x];
    if (idx < NNODES) {
        off[idx] = excl;
        cur[idx] = excl;
        inv[idx] = 1.0f / ((float)v + 1.0f);
        cnt[idx] = 0;
    }
}

// ---------------- fill CSR buckets ----------------
__global__ void fill_kernel(const int* __restrict__ src, const int* __restrict__ tgt,
                            int* __restrict__ cur, int* __restrict__ srcs, int E)
{
    int i = (blockIdx.x * blockDim.x + threadIdx.x) * 4;
    if (i + 4 <= E) {
        int t0 = tgt[i], t1 = tgt[i + 1], t2 = tgt[i + 2], t3 = tgt[i + 3];
        int s0 = src[i], s1 = src[i + 1], s2 = src[i + 2], s3 = src[i + 3];
        int p0 = atomicAdd(&cur[t0], 1);
        int p1 = atomicAdd(&cur[t1], 1);
        int p2 = atomicAdd(&cur[t2], 1);
        int p3 = atomicAdd(&cur[t3], 1);
        srcs[p0] = s0;
        srcs[p1] = s1;
        srcs[p2] = s2;
        srcs[p3] = s3;
    } else {
        for (; i < E; i++) {
            int p = atomicAdd(&cur[tgt[i]], 1);
            srcs[p] = src[i];
        }
    }
}

// ---------------- 128-wide fused gather + combine (propagation in z-space) ----------------
// One warp per node; each lane owns 4 floats. Register-lean (latency-bound).
// PDL consumer (waits on predecessor grid) + producer (triggers successor).
__device__ __forceinline__ void acc_bf16x4(float4& acc, uint2 p) {
    __nv_bfloat162 lo = *reinterpret_cast<__nv_bfloat162*>(&p.x);
    __nv_bfloat162 hi = *reinterpret_cast<__nv_bfloat162*>(&p.y);
    float2 f0 = __bfloat1622float2(lo);
    float2 f1 = __bfloat1622float2(hi);
    acc.x += f0.x; acc.y += f0.y; acc.z += f1.x; acc.w += f1.y;
}

__global__ __launch_bounds__(256) void gather_combine128_kernel(
    const float* __restrict__ zin, const __nv_bfloat16* __restrict__ zbin,
    float* __restrict__ zout, __nv_bfloat16* __restrict__ zbout,
    const float* __restrict__ b2,        // non-null => final pass: +bias, relu, no shadow
    const int* __restrict__ off, const int* __restrict__ srcs,
    const float* __restrict__ inv)
{
    int node = blockIdx.x * 8 + (threadIdx.x >> 5);
    int c = (threadIdx.x & 31) << 2;

    // prelude (CSR is ready before this kernel's PDL edge): fetch range
    int beg = 0, end = 0;
    if (node < NNODES) {
        beg = __ldg(off + node);
        end = __ldg(off + node + 1);
    }

    // wait for predecessor grid (zin/zbin producer) to fully complete
    cudaGridDependencySynchronize();

    if (node >= NNODES) return;

    float4 acc = make_float4(0.f, 0.f, 0.f, 0.f);
    int i = beg;
    for (; i + 4 <= end; i += 4) {
        int s0 = __ldg(srcs + i);
        int s1 = __ldg(srcs + i + 1);
        int s2 = __ldg(srcs + i + 2);
        int s3 = __ldg(srcs + i + 3);
        uint2 p0 = *reinterpret_cast<const uint2*>(zbin + (size_t)s0 * OUT_D + c);
        uint2 p1 = *reinterpret_cast<const uint2*>(zbin + (size_t)s1 * OUT_D + c);
        uint2 p2 = *reinterpret_cast<const uint2*>(zbin + (size_t)s2 * OUT_D + c);
        uint2 p3 = *reinterpret_cast<const uint2*>(zbin + (size_t)s3 * OUT_D + c);
        acc_bf16x4(acc, p0);
        acc_bf16x4(acc, p1);
        acc_bf16x4(acc, p2);
        acc_bf16x4(acc, p3);
    }
    for (; i < end; i++) {
        int s0 = __ldg(srcs + i);
        uint2 p0 = *reinterpret_cast<const uint2*>(zbin + (size_t)s0 * OUT_D + c);
        acc_bf16x4(acc, p0);
    }

    float sc = 0.3f * inv[node];
    float4 zv = *reinterpret_cast<const float4*>(zin + (size_t)node * OUT_D + c);
    zv.x = 0.7f * zv.x + sc * acc.x;
    zv.y = 0.7f * zv.y + sc * acc.y;
    zv.z = 0.7f * zv.z + sc * acc.z;
    zv.w = 0.7f * zv.w + sc * acc.w;

    if (b2) {
        float4 bv = *reinterpret_cast<const float4*>(b2 + c);
        zv.x = fmaxf(zv.x + bv.x, 0.f);
        zv.y = fmaxf(zv.y + bv.y, 0.f);
        zv.z = fmaxf(zv.z + bv.z, 0.f);
        zv.w = fmaxf(zv.w + bv.w, 0.f);
        *reinterpret_cast<float4*>(zout + (size_t)node * OUT_D + c) = zv;
    } else {
        *reinterpret_cast<float4*>(zout + (size_t)node * OUT_D + c) = zv;
        uint2 pk;
        __nv_bfloat162 lo = __floats2bfloat162_rn(zv.x, zv.y);
        __nv_bfloat162 hi = __floats2bfloat162_rn(zv.z, zv.w);
        pk.x = *reinterpret_cast<uint32_t*>(&lo);
        pk.y = *reinterpret_cast<uint32_t*>(&hi);
        *reinterpret_cast<uint2*>(zbout + (size_t)node * OUT_D + c) = pk;
    }

    cudaTriggerProgrammaticLaunchCompletion();
}

// ---------------- tf32 tensor-core GEMM (double-buffered regs, single-stage smem, PDL) ----------------
#define GBM 128
#define GBN 64
#define GBK 32
#define SKA 36

__device__ __forceinline__ uint32_t f2tf32(float x) {
    uint32_t r;
    asm("cvt.rna.tf32.f32 %0, %1;" : "=r"(r) : "f"(x));
    return r;
}

__device__ __forceinline__ void mma_tf32(float* c, const uint32_t* a, const uint32_t* b) {
    asm volatile(
        "mma.sync.aligned.m16n8k8.row.col.f32.tf32.tf32.f32 "
        "{%0,%1,%2,%3}, {%4,%5,%6,%7}, {%8,%9}, {%0,%1,%2,%3};"
        : "+f"(c[0]), "+f"(c[1]), "+f"(c[2]), "+f"(c[3])
        : "r"(a[0]), "r"(a[1]), "r"(a[2]), "r"(a[3]), "r"(b[0]), "r"(b[1]));
}

__global__ __launch_bounds__(256) void gemm_tf32_kernel(
    const float* __restrict__ A, const float* __restrict__ B,
    const float* __restrict__ bias,          // nullable
    float* __restrict__ C,
    __nv_bfloat16* __restrict__ Cb,          // nullable
    int M, int N, int K, int do_relu)
{
    __shared__ uint32_t As[GBM][SKA];
    __shared__ uint32_t Bs[GBN][SKA];

    const int tid  = threadIdx.x;
    const int lane = tid & 31;
    const int warp = tid >> 5;
    const int wm = warp >> 1;
    const int wn = warp & 1;
    const int g   = lane >> 2;
    const int tig = lane & 3;
    const int m0 = blockIdx.y * GBM;
    const int n0 = blockIdx.x * GBN;

    const int ar = tid >> 3;
    const int ac4 = (tid & 7) << 2;

    // wait for predecessor (A producer) before reading; no-op when launched normally
    cudaGridDependencySynchronize();

    float acc[2][4][4];
#pragma unroll
    for (int mm = 0; mm < 2; mm++)
#pragma unroll
        for (int nn = 0; nn < 4; nn++)
#pragma unroll
            for (int q = 0; q < 4; q++) acc[mm][nn][q] = 0.0f;

    float4 ra[4], rb[2];
#pragma unroll
    for (int it = 0; it < 4; it++) {
        int r = ar + it * 32;
        int gm = m0 + r;
        ra[it] = (gm < M) ? *reinterpret_cast<const float4*>(A + (size_t)gm * K + ac4)
                          : make_float4(0.f, 0.f, 0.f, 0.f);
    }
#pragma unroll
    for (int it = 0; it < 2; it++) {
        int r = ar + it * 32;
        rb[it] = *reinterpret_cast<const float4*>(B + (size_t)(n0 + r) * K + ac4);
    }

    for (int k0 = 0; k0 < K; k0 += GBK) {
#pragma unroll
        for (int it = 0; it < 4; it++) {
            int r = ar + it * 32;
            As[r][ac4 + 0] = f2tf32(ra[it].x);
            As[r][ac4 + 1] = f2tf32(ra[it].y);
            As[r][ac4 + 2] = f2tf32(ra[it].z);
            As[r][ac4 + 3] = f2tf32(ra[it].w);
        }
#pragma unroll
        for (int it = 0; it < 2; it++) {
            int r = ar + it * 32;
            Bs[r][ac4 + 0] = f2tf32(rb[it].x);
            Bs[r][ac4 + 1] = f2tf32(rb[it].y);
            Bs[r][ac4 + 2] = f2tf32(rb[it].z);
            Bs[r][ac4 + 3] = f2tf32(rb[it].w);
        }
        __syncthreads();

        int kn = k0 + GBK;
        if (kn < K) {
#pragma unroll
            for (int it = 0; it < 4; it++) {
                int r = ar + it * 32;
                int gm = m0 + r;
                ra[it] = (gm < M) ? *reinterpret_cast<const float4*>(A + (size_t)gm * K + kn + ac4)
                                  : make_float4(0.f, 0.f, 0.f, 0.f);
            }
#pragma unroll
            for (int it = 0; it < 2; it++) {
                int r = ar + it * 32;
                rb[it] = *reinterpret_cast<const float4*>(B + (size_t)(n0 + r) * K + kn + ac4);
            }
        }

#pragma unroll
        for (int kk = 0; kk < GBK; kk += 8) {
            uint32_t af[2][4];
#pragma unroll
            for (int mm = 0; mm < 2; mm++) {
                int row = wm * 32 + mm * 16 + g;
                af[mm][0] = As[row][kk + tig];
                af[mm][1] = As[row + 8][kk + tig];
                af[mm][2] = As[row][kk + tig + 4];
                af[mm][3] = As[row + 8][kk + tig + 4];
            }
            uint32_t bf[4][2];
#pragma unroll
            for (int nn = 0; nn < 4; nn++) {
                int col = wn * 32 + nn * 8 + g;
                bf[nn][0] = Bs[col][kk + tig];
                bf[nn][1] = Bs[col][kk + tig + 4];
            }
#pragma unroll
            for (int mm = 0; mm < 2; mm++)
#pragma unroll
                for (int nn = 0; nn < 4; nn++)
                    mma_tf32(acc[mm][nn], af[mm], bf[nn]);
        }
        __syncthreads();
    }

#pragma unroll
    for (int mm = 0; mm < 2; mm++) {
        int r0 = m0 + wm * 32 + mm * 16 + g;
#pragma unroll
        for (int nn = 0; nn < 4; nn++) {
            int col = n0 + wn * 32 + nn * 8 + tig * 2;
            float b0 = bias ? bias[col]     : 0.f;
            float b1 = bias ? bias[col + 1] : 0.f;
#pragma unroll
            for (int half = 0; half < 2; half++) {
                int r = r0 + half * 8;
                if (r >= M) continue;
                float v0 = acc[mm][nn][half * 2 + 0] + b0;
                float v1 = acc[mm][nn][half * 2 + 1] + b1;
                if (do_relu) { v0 = fmaxf(v0, 0.f); v1 = fmaxf(v1, 0.f); }
                C[(size_t)r * N + col]     = v0;
                C[(size_t)r * N + col + 1] = v1;
                if (Cb) {
                    __nv_bfloat162 p = __floats2bfloat162_rn(v0, v1);
                    *reinterpret_cast<uint32_t*>(Cb + (size_t)r * N + col) =
                        *reinterpret_cast<uint32_t*>(&p);
                }
            }
        }
    }

    cudaTriggerProgrammaticLaunchCompletion();
}

// ---------------- transpose Wa1 (64x128) -> WaT (128x64) ----------------
__global__ void transpose_wa1_kernel(const float* __restrict__ Wa1, float* __restrict__ WaT) {
    int idx = blockIdx.x * blockDim.x + threadIdx.x;
    if (idx >= OUT_D * ATT_H) return;
    int k = idx / ATT_H;
    int j = idx % ATT_H;
    WaT[idx] = Wa1[j * OUT_D + k];
}

// ---------------- attention: warp per node (lean, PDL consumer) ----------------
__global__ __launch_bounds__(256) void attention_kernel(
    const float* __restrict__ out, const float* __restrict__ WaT,
    const float* __restrict__ ba1, const float* __restrict__ Wa2,
    const float* __restrict__ ba2, float* __restrict__ att, int N)
{
    int warp = (blockIdx.x * blockDim.x + threadIdx.x) >> 5;
    int lane = threadIdx.x & 31;

    // prelude independent of `out`: bias + Wa2 loads warm while predecessor drains
    float acc0 = ba1[lane];
    float acc1 = ba1[lane + 32];
    float w2a = Wa2[lane];
    float w2b = Wa2[lane + 32];
    float bb2 = ba2[0];

    cudaGridDependencySynchronize();

    if (warp >= N) return;
    const float* o = out + (size_t)warp * OUT_D;
#pragma unroll 4
    for (int k = 0; k < OUT_D; k++) {
        float ov = __ldg(o + k);
        acc0 = fmaf(WaT[k * ATT_H + lane],      ov, acc0);
        acc1 = fmaf(WaT[k * ATT_H + lane + 32], ov, acc1);
    }
    acc0 = fmaxf(acc0, 0.0f) * w2a;
    acc1 = fmaxf(acc1, 0.0f) * w2b;
    float s = acc0 + acc1;
#pragma unroll
    for (int off = 16; off; off >>= 1) s += __shfl_xor_sync(0xffffffffu, s, off);
    if (lane == 0) att[warp] = 1.0f / (1.0f + expf(-(s + bb2)));
}

// ---------------- PDL launch helper ----------------
template <typename F, typename... Args>
static inline void launch_pdl(F kern, dim3 grid, dim3 block, Args... args) {
    cudaLaunchConfig_t cfg = {};
    cfg.gridDim = grid;
    cfg.blockDim = block;
    cfg.dynamicSmemBytes = 0;
    cfg.stream = 0;
    cudaLaunchAttribute attr[1];
    attr[0].id = cudaLaunchAttributeProgrammaticStreamSerialization;
    attr[0].val.programmaticStreamSerializationAllowed = 1;
    cfg.attrs = attr;
    cfg.numAttrs = 1;
    cudaLaunchKernelEx(&cfg, kern, args...);
}

// ---------------- launch ----------------
extern "C" void kernel_launch(void* const* d_in, const int* in_sizes, int n_in,
                              void* d_out, int out_size)
{
    const float* x    = (const float*)d_in[0];
    const int*   ei   = (const int*)d_in[1];     // (2, E) int32: [src | tgt]
    const float* W1   = (const float*)d_in[2];
    const float* b1   = (const float*)d_in[3];
    const float* W2   = (const float*)d_in[4];
    const float* b2   = (const float*)d_in[5];
    const float* Wa1  = (const float*)d_in[6];
    const float* ba1  = (const float*)d_in[7];
    const float* Wa2  = (const float*)d_in[8];
    const float* ba2  = (const float*)d_in[9];

    const int E = in_sizes[1] / 2;
    const int* src = ei;
    const int* tgt = ei + E;

    float* out_ptr = (float*)d_out;                        // (N, 128)
    float* att_ptr = out_ptr + (size_t)NNODES * OUT_D;     // (N, 1)

    float*         h_p;    cudaGetSymbolAddress((void**)&h_p,    g_h);
    float*         z_p;    cudaGetSymbolAddress((void**)&z_p,    g_z);
    float*         z2_p;   cudaGetSymbolAddress((void**)&z2_p,   g_z2);
    __nv_bfloat16* zb_p;   cudaGetSymbolAddress((void**)&zb_p,   g_zb);
    __nv_bfloat16* zb2_p;  cudaGetSymbolAddress((void**)&zb2_p,  g_zb2);
    float*         inv_p;  cudaGetSymbolAddress((void**)&inv_p,  g_inv);
    int*           cnt_p;  cudaGetSymbolAddress((void**)&cnt_p,  g_cnt);
    int*           off_p;  cudaGetSymbolAddress((void**)&off_p,  g_off);
    int*           cur_p;  cudaGetSymbolAddress((void**)&cur_p,  g_cur);
    int*           bsum_p; cudaGetSymbolAddress((void**)&bsum_p, g_bsum);
    int*           bofs_p; cudaGetSymbolAddress((void**)&bofs_p, g_bofs);
    int*           srcs_p; cudaGetSymbolAddress((void**)&srcs_p, g_srcs);
    float*         wat_p;  cudaGetSymbolAddress((void**)&wat_p,  g_WaT);

    // --- fork side stream: CSR build + Wa1 transpose (hides under GEMMs) ---
    cudaStream_t side;
    cudaStreamCreateWithFlags(&side, cudaStreamNonBlocking);
    cudaEvent_t ev_fork, ev_csr;
    cudaEventCreateWithFlags(&ev_fork, cudaEventDisableTiming);
    cudaEventCreateWithFlags(&ev_csr,  cudaEventDisableTiming);

    cudaEventRecord(ev_fork, 0);
    cudaStreamWaitEvent(side, ev_fork, 0);

    transpose_wa1_kernel<<<(OUT_D * ATT_H + 255) / 256, 256, 0, side>>>(Wa1, wat_p);
    count_kernel<<<(E / 4 + 255) / 256, 256, 0, side>>>(tgt, cnt_p, E);
    scan1_kernel<<<SCAN_BLOCKS, SCAN_TPB, 0, side>>>(cnt_p, bsum_p);
    scan2_kernel<<<1, 64, 0, side>>>(bsum_p, bofs_p, off_p);
    scan3_kernel<<<SCAN_BLOCKS, SCAN_TPB, 0, side>>>(cnt_p, bofs_p, off_p, cur_p, inv_p);
    fill_kernel<<<(E / 4 + 255) / 256, 256, 0, side>>>(src, tgt, cur_p, srcs_p, E);
    cudaEventRecord(ev_csr, side);

    // main: h = relu(x @ W1^T + b1)  — first in chain, normal launch
    {
        dim3 grid(HID / GBN, (NNODES + GBM - 1) / GBM);
        gemm_tf32_kernel<<<grid, 256>>>(x, W1, b1, h_p, (__nv_bfloat16*)nullptr,
                                        NNODES, HID, F_IN, 1);
    }
    // main: z = h @ W2^T  (PDL on gemm1)
    {
        dim3 grid(OUT_D / GBN, (NNODES + GBM - 1) / GBM);
        launch_pdl(gemm_tf32_kernel, grid, dim3(256),
                   h_p, (const float*)W2, (const float*)nullptr, z_p, zb_p,
                   NNODES, OUT_D, HID, 0);
    }

    cudaStreamWaitEvent(0, ev_csr, 0);

    // propagation in z-space (PDL chain): z2 = P z ; out = relu(P z2 + b2)
    {
        int gblocks = (NNODES + 7) / 8;
        launch_pdl(gather_combine128_kernel, dim3(gblocks), dim3(256),
                   (const float*)z_p, (const __nv_bfloat16*)zb_p, z2_p, zb2_p,
                   (const float*)nullptr,
                   (const int*)off_p, (const int*)srcs_p, (const float*)inv_p);
        launch_pdl(gather_combine128_kernel, dim3(gblocks), dim3(256),
                   (const float*)z2_p, (const __nv_bfloat16*)zb2_p, out_ptr,
                   (__nv_bfloat16*)nullptr, (const float*)b2,
                   (const int*)off_p, (const int*)srcs_p, (const float*)inv_p);
    }

    // attention (PDL on gather pass 2)
    launch_pdl(attention_kernel, dim3((NNODES * 32 + 255) / 256), dim3(256),
               (const float*)out_ptr, (const float*)wat_p, ba1, Wa2, ba2,
               att_ptr, NNODES);

    cudaEventDestroy(ev_fork);
    cudaEventDestroy(ev_csr);
    cudaStreamDestroy(side);
}

// round 16
// speedup vs baseline: 1.1120x; 1.0048x over previous
#include <cuda_runtime.h>
#include <cuda_bf16.h>
#include <math.h>
#include <stdint.h>

// ---------------- problem constants ----------------
#define NNODES   10000
#define F_IN     384
#define HID      256
#define OUT_D    128
#define ATT_H    64
#define EDGES_MAX 320000

#define SCAN_BLOCKS 40
#define SCAN_TPB    256   // 40*256 = 10240 >= NNODES

// ---------------- scratch (device globals; no allocation allowed) ----------------
__device__ float           g_h  [NNODES * HID];     // relu(x W1^T + b1), 256-wide
__device__ float           g_z  [NNODES * OUT_D];   // h @ W2^T (pre-bias/relu), 128-wide
__device__ float           g_z2 [NNODES * OUT_D];
__device__ __nv_bfloat16   g_zb [NNODES * OUT_D];   // bf16 shadows for neighbor reads
__device__ __nv_bfloat16   g_zb2[NNODES * OUT_D];
__device__ float g_inv[NNODES];
__device__ int   g_cnt[NNODES];          // zero-init; re-zeroed by scan3 each launch
__device__ int   g_off[NNODES + 1];
__device__ int   g_cur[NNODES];
__device__ int   g_bsum[SCAN_BLOCKS];
__device__ int   g_bofs[SCAN_BLOCKS];
__device__ int   g_srcs[EDGES_MAX];
__device__ float g_WaT[OUT_D * ATT_H];   // Wa1 transposed

// ---------------- count in-degree, 4 edges/thread ----------------
__global__ void count_kernel(const int* __restrict__ tgt, int* __restrict__ cnt, int E) {
    int i = (blockIdx.x * blockDim.x + threadIdx.x) * 4;
    if (i + 4 <= E) {
        int t0 = tgt[i], t1 = tgt[i + 1], t2 = tgt[i + 2], t3 = tgt[i + 3];
        atomicAdd(&cnt[t0], 1);
        atomicAdd(&cnt[t1], 1);
        atomicAdd(&cnt[t2], 1);
        atomicAdd(&cnt[t3], 1);
    } else {
        for (; i < E; i++) atomicAdd(&cnt[tgt[i]], 1);
    }
}

// ---------------- scan phase 1 ----------------
__global__ __launch_bounds__(SCAN_TPB) void scan1_kernel(
    const int* __restrict__ cnt, int* __restrict__ bsum)
{
    __shared__ int wsum[SCAN_TPB / 32];
    int idx = blockIdx.x * SCAN_TPB + threadIdx.x;
    int v = (idx < NNODES) ? cnt[idx] : 0;
    int lane = threadIdx.x & 31;
    int warp = threadIdx.x >> 5;
#pragma unroll
    for (int d = 16; d; d >>= 1) v += __shfl_xor_sync(0xffffffffu, v, d);
    if (lane == 0) wsum[warp] = v;
    __syncthreads();
    if (threadIdx.x == 0) {
        int s = 0;
#pragma unroll
        for (int w = 0; w < SCAN_TPB / 32; w++) s += wsum[w];
        bsum[blockIdx.x] = s;
    }
}

// ---------------- scan phase 2 ----------------
__global__ void scan2_kernel(const int* __restrict__ bsum, int* __restrict__ bofs,
                             int* __restrict__ off)
{
    int lane = threadIdx.x;
    int v = (lane < SCAN_BLOCKS) ? bsum[lane] : 0;
    int lane32 = lane & 31;
    int half = lane >> 5;
    int s = v;
#pragma unroll
    for (int d = 1; d < 32; d <<= 1) {
        int t = __shfl_up_sync(0xffffffffu, s, d);
        if (lane32 >= d) s += t;
    }
    __shared__ int w0tot;
    if (lane == 31) w0tot = s;
    __syncthreads();
    int incl = s + (half ? w0tot : 0);
    if (lane < SCAN_BLOCKS) bofs[lane] = incl - v;
    if (lane == SCAN_BLOCKS - 1) off[NNODES] = incl;
}

// ---------------- scan phase 3 ----------------
__global__ __launch_bounds__(SCAN_TPB) void scan3_kernel(
    int* __restrict__ cnt, const int* __restrict__ bofs,
    int* __restrict__ off, int* __restrict__ cur, float* __restrict__ inv)
{
    __shared__ int wsum[SCAN_TPB / 32];
    int idx = blockIdx.x * SCAN_TPB + threadIdx.x;
    int lane = threadIdx.x & 31;
    int warp = threadIdx.x >> 5;
    int v = (idx < NNODES) ? cnt[idx] : 0;

    int s = v;
#pragma unroll
    for (int d = 1; d < 32; d <<= 1) {
        int t = __shfl_up_sync(0xffffffffu, s, d);
        if (lane >= d) s += t;
    }
    if (lane == 31) wsum[warp] = s;
    __syncthreads();
    if (warp == 0) {
        int ws = (lane < SCAN_TPB / 32) ? wsum[lane] : 0;
#pragma unroll
        for (int d = 1; d < SCAN_TPB / 32; d <<= 1) {
            int t = __shfl_up_sync(0xffffffffu, ws, d);
            if (lane >= d) ws += t;
        }
        if (lane < SCAN_TPB / 32) wsum[lane] = ws;
    }
    __syncthreads();
    int excl = s - v + (warp ? wsum[warp - 1] : 0) + bofs[blockIdx.x];
    if (idx < NNODES) {
        off[idx] = excl;
        cur[idx] = excl;
        inv[idx] = 1.0f / ((float)v + 1.0f);
        cnt[idx] = 0;
    }
}

// ---------------- fill CSR buckets ----------------
__global__ void fill_kernel(const int* __restrict__ src, const int* __restrict__ tgt,
                            int* __restrict__ cur, int* __restrict__ srcs, int E)
{
    int i = (blockIdx.x * blockDim.x + threadIdx.x) * 4;
    if (i + 4 <= E) {
        int t0 = tgt[i], t1 = tgt[i + 1], t2 = tgt[i + 2], t3 = tgt[i + 3];
        int s0 = src[i], s1 = src[i + 1], s2 = src[i + 2], s3 = src[i + 3];
        int p0 = atomicAdd(&cur[t0], 1);
        int p1 = atomicAdd(&cur[t1], 1);
        int p2 = atomicAdd(&cur[t2], 1);
        int p3 = atomicAdd(&cur[t3], 1);
        srcs[p0] = s0;
        srcs[p1] = s1;
        srcs[p2] = s2;
        srcs[p3] = s3;
    } else {
        for (; i < E; i++) {
            int p = atomicAdd(&cur[tgt[i]], 1);
            srcs[p] = src[i];
        }
    }
}

// ---------------- 128-wide gather + combine: 2 warps per node (split neighbor list) ----------------
// 256 thr = 8 warps = 4 nodes. Odd warp sums the upper half of the neighbor list into
// smem; even warp sums the lower half, adds the partial, applies self-combine (+epilogue).
__device__ __forceinline__ void acc_bf16x4(float4& acc, uint2 p) {
    __nv_bfloat162 lo = *reinterpret_cast<__nv_bfloat162*>(&p.x);
    __nv_bfloat162 hi = *reinterpret_cast<__nv_bfloat162*>(&p.y);
    float2 f0 = __bfloat1622float2(lo);
    float2 f1 = __bfloat1622float2(hi);
    acc.x += f0.x; acc.y += f0.y; acc.z += f1.x; acc.w += f1.y;
}

__global__ __launch_bounds__(256) void gather_combine128_kernel(
    const float* __restrict__ zin, const __nv_bfloat16* __restrict__ zbin,
    float* __restrict__ zout, __nv_bfloat16* __restrict__ zbout,
    const float* __restrict__ b2,        // non-null => final pass: +bias, relu, no shadow
    const int* __restrict__ off, const int* __restrict__ srcs,
    const float* __restrict__ inv)
{
    __shared__ float sacc[4][OUT_D];

    const int warp = threadIdx.x >> 5;
    const int nloc = warp >> 1;          // node within block: 0..3
    const int half = warp & 1;           // which half of the neighbor list
    const int lane = threadIdx.x & 31;
    const int c = lane << 2;
    const int node = blockIdx.x * 4 + nloc;

    // prelude (CSR ready before the PDL edge): fetch range + split point
    int lo = 0, hi = 0;
    if (node < NNODES) {
        int beg = __ldg(off + node);
        int end = __ldg(off + node + 1);
        int mid = beg + ((end - beg + 1) >> 1);
        lo = half ? mid : beg;
        hi = half ? end : mid;
    }

    // wait for predecessor grid (zin/zbin producer)
    cudaGridDependencySynchronize();

    float4 acc = make_float4(0.f, 0.f, 0.f, 0.f);
    int i = lo;
    for (; i + 4 <= hi; i += 4) {
        int s0 = __ldg(srcs + i);
        int s1 = __ldg(srcs + i + 1);
        int s2 = __ldg(srcs + i + 2);
        int s3 = __ldg(srcs + i + 3);
        uint2 p0 = *reinterpret_cast<const uint2*>(zbin + (size_t)s0 * OUT_D + c);
        uint2 p1 = *reinterpret_cast<const uint2*>(zbin + (size_t)s1 * OUT_D + c);
        uint2 p2 = *reinterpret_cast<const uint2*>(zbin + (size_t)s2 * OUT_D + c);
        uint2 p3 = *reinterpret_cast<const uint2*>(zbin + (size_t)s3 * OUT_D + c);
        acc_bf16x4(acc, p0);
        acc_bf16x4(acc, p1);
        acc_bf16x4(acc, p2);
        acc_bf16x4(acc, p3);
    }
    for (; i < hi; i++) {
        int s0 = __ldg(srcs + i);
        uint2 p0 = *reinterpret_cast<const uint2*>(zbin + (size_t)s0 * OUT_D + c);
        acc_bf16x4(acc, p0);
    }

    // odd warp deposits its partial; even warp combines after the barrier
    if (half) *reinterpret_cast<float4*>(&sacc[nloc][c]) = acc;
    __syncthreads();
    if (half || node >= NNODES) return;

    float4 part = *reinterpret_cast<const float4*>(&sacc[nloc][c]);
    acc.x += part.x; acc.y += part.y; acc.z += part.z; acc.w += part.w;

    float sc = 0.3f * inv[node];
    float4 zv = *reinterpret_cast<const float4*>(zin + (size_t)node * OUT_D + c);
    zv.x = 0.7f * zv.x + sc * acc.x;
    zv.y = 0.7f * zv.y + sc * acc.y;
    zv.z = 0.7f * zv.z + sc * acc.z;
    zv.w = 0.7f * zv.w + sc * acc.w;

    if (b2) {
        float4 bv = *reinterpret_cast<const float4*>(b2 + c);
        zv.x = fmaxf(zv.x + bv.x, 0.f);
        zv.y = fmaxf(zv.y + bv.y, 0.f);
        zv.z = fmaxf(zv.z + bv.z, 0.f);
        zv.w = fmaxf(zv.w + bv.w, 0.f);
        *reinterpret_cast<float4*>(zout + (size_t)node * OUT_D + c) = zv;
    } else {
        *reinterpret_cast<float4*>(zout + (size_t)node * OUT_D + c) = zv;
        uint2 pk;
        __nv_bfloat162 blo = __floats2bfloat162_rn(zv.x, zv.y);
        __nv_bfloat162 bhi = __floats2bfloat162_rn(zv.z, zv.w);
        pk.x = *reinterpret_cast<uint32_t*>(&blo);
        pk.y = *reinterpret_cast<uint32_t*>(&bhi);
        *reinterpret_cast<uint2*>(zbout + (size_t)node * OUT_D + c) = pk;
    }

    cudaTriggerProgrammaticLaunchCompletion();
}

// ---------------- tf32 tensor-core GEMM (double-buffered regs, single-stage smem, PDL) ----------------
#define GBM 128
#define GBN 64
#define GBK 32
#define SKA 36

__device__ __forceinline__ uint32_t f2tf32(float x) {
    uint32_t r;
    asm("cvt.rna.tf32.f32 %0, %1;" : "=r"(r) : "f"(x));
    return r;
}

__device__ __forceinline__ void mma_tf32(float* c, const uint32_t* a, const uint32_t* b) {
    asm volatile(
        "mma.sync.aligned.m16n8k8.row.col.f32.tf32.tf32.f32 "
        "{%0,%1,%2,%3}, {%4,%5,%6,%7}, {%8,%9}, {%0,%1,%2,%3};"
        : "+f"(c[0]), "+f"(c[1]), "+f"(c[2]), "+f"(c[3])
        : "r"(a[0]), "r"(a[1]), "r"(a[2]), "r"(a[3]), "r"(b[0]), "r"(b[1]));
}

__global__ __launch_bounds__(256) void gemm_tf32_kernel(
    const float* __restrict__ A, const float* __restrict__ B,
    const float* __restrict__ bias,          // nullable
    float* __restrict__ C,
    __nv_bfloat16* __restrict__ Cb,          // nullable
    int M, int N, int K, int do_relu)
{
    __shared__ uint32_t As[GBM][SKA];
    __shared__ uint32_t Bs[GBN][SKA];

    const int tid  = threadIdx.x;
    const int lane = tid & 31;
    const int warp = tid >> 5;
    const int wm = warp >> 1;
    const int wn = warp & 1;
    const int g   = lane >> 2;
    const int tig = lane & 3;
    const int m0 = blockIdx.y * GBM;
    const int n0 = blockIdx.x * GBN;

    const int ar = tid >> 3;
    const int ac4 = (tid & 7) << 2;

    cudaGridDependencySynchronize();

    float acc[2][4][4];
#pragma unroll
    for (int mm = 0; mm < 2; mm++)
#pragma unroll
        for (int nn = 0; nn < 4; nn++)
#pragma unroll
            for (int q = 0; q < 4; q++) acc[mm][nn][q] = 0.0f;

    float4 ra[4], rb[2];
#pragma unroll
    for (int it = 0; it < 4; it++) {
        int r = ar + it * 32;
        int gm = m0 + r;
        ra[it] = (gm < M) ? *reinterpret_cast<const float4*>(A + (size_t)gm * K + ac4)
                          : make_float4(0.f, 0.f, 0.f, 0.f);
    }
#pragma unroll
    for (int it = 0; it < 2; it++) {
        int r = ar + it * 32;
        rb[it] = *reinterpret_cast<const float4*>(B + (size_t)(n0 + r) * K + ac4);
    }

    for (int k0 = 0; k0 < K; k0 += GBK) {
#pragma unroll
        for (int it = 0; it < 4; it++) {
            int r = ar + it * 32;
            As[r][ac4 + 0] = f2tf32(ra[it].x);
            As[r][ac4 + 1] = f2tf32(ra[it].y);
            As[r][ac4 + 2] = f2tf32(ra[it].z);
            As[r][ac4 + 3] = f2tf32(ra[it].w);
        }
#pragma unroll
        for (int it = 0; it < 2; it++) {
            int r = ar + it * 32;
            Bs[r][ac4 + 0] = f2tf32(rb[it].x);
            Bs[r][ac4 + 1] = f2tf32(rb[it].y);
            Bs[r][ac4 + 2] = f2tf32(rb[it].z);
            Bs[r][ac4 + 3] = f2tf32(rb[it].w);
        }
        __syncthreads();

        int kn = k0 + GBK;
        if (kn < K) {
#pragma unroll
            for (int it = 0; it < 4; it++) {
                int r = ar + it * 32;
                int gm = m0 + r;
                ra[it] = (gm < M) ? *reinterpret_cast<const float4*>(A + (size_t)gm * K + kn + ac4)
                                  : make_float4(0.f, 0.f, 0.f, 0.f);
            }
#pragma unroll
            for (int it = 0; it < 2; it++) {
                int r = ar + it * 32;
                rb[it] = *reinterpret_cast<const float4*>(B + (size_t)(n0 + r) * K + kn + ac4);
            }
        }

#pragma unroll
        for (int kk = 0; kk < GBK; kk += 8) {
            uint32_t af[2][4];
#pragma unroll
            for (int mm = 0; mm < 2; mm++) {
                int row = wm * 32 + mm * 16 + g;
                af[mm][0] = As[row][kk + tig];
                af[mm][1] = As[row + 8][kk + tig];
                af[mm][2] = As[row][kk + tig + 4];
                af[mm][3] = As[row + 8][kk + tig + 4];
            }
            uint32_t bf[4][2];
#pragma unroll
            for (int nn = 0; nn < 4; nn++) {
                int col = wn * 32 + nn * 8 + g;
                bf[nn][0] = Bs[col][kk + tig];
                bf[nn][1] = Bs[col][kk + tig + 4];
            }
#pragma unroll
            for (int mm = 0; mm < 2; mm++)
#pragma unroll
                for (int nn = 0; nn < 4; nn++)
                    mma_tf32(acc[mm][nn], af[mm], bf[nn]);
        }
        __syncthreads();
    }

#pragma unroll
    for (int mm = 0; mm < 2; mm++) {
        int r0 = m0 + wm * 32 + mm * 16 + g;
#pragma unroll
        for (int nn = 0; nn < 4; nn++) {
            int col = n0 + wn * 32 + nn * 8 + tig * 2;
            float b0 = bias ? bias[col]     : 0.f;
            float b1 = bias ? bias[col + 1] : 0.f;
#pragma unroll
            for (int half = 0; half < 2; half++) {
                int r = r0 + half * 8;
                if (r >= M) continue;
                float v0 = acc[mm][nn][half * 2 + 0] + b0;
                float v1 = acc[mm][nn][half * 2 + 1] + b1;
                if (do_relu) { v0 = fmaxf(v0, 0.f); v1 = fmaxf(v1, 0.f); }
                C[(size_t)r * N + col]     = v0;
                C[(size_t)r * N + col + 1] = v1;
                if (Cb) {
                    __nv_bfloat162 p = __floats2bfloat162_rn(v0, v1);
                    *reinterpret_cast<uint32_t*>(Cb + (size_t)r * N + col) =
                        *reinterpret_cast<uint32_t*>(&p);
                }
            }
        }
    }

    cudaTriggerProgrammaticLaunchCompletion();
}

// ---------------- transpose Wa1 (64x128) -> WaT (128x64) ----------------
__global__ void transpose_wa1_kernel(const float* __restrict__ Wa1, float* __restrict__ WaT) {
    int idx = blockIdx.x * blockDim.x + threadIdx.x;
    if (idx >= OUT_D * ATT_H) return;
    int k = idx / ATT_H;
    int j = idx % ATT_H;
    WaT[idx] = Wa1[j * OUT_D + k];
}

// ---------------- attention: warp per node (lean, PDL consumer) ----------------
__global__ __launch_bounds__(256) void attention_kernel(
    const float* __restrict__ out, const float* __restrict__ WaT,
    const float* __restrict__ ba1, const float* __restrict__ Wa2,
    const float* __restrict__ ba2, float* __restrict__ att, int N)
{
    int warp = (blockIdx.x * blockDim.x + threadIdx.x) >> 5;
    int lane = threadIdx.x & 31;

    float acc0 = ba1[lane];
    float acc1 = ba1[lane + 32];
    float w2a = Wa2[lane];
    float w2b = Wa2[lane + 32];
    float bb2 = ba2[0];

    cudaGridDependencySynchronize();

    if (warp >= N) return;
    const float* o = out + (size_t)warp * OUT_D;
#pragma unroll 4
    for (int k = 0; k < OUT_D; k++) {
        float ov = __ldg(o + k);
        acc0 = fmaf(WaT[k * ATT_H + lane],      ov, acc0);
        acc1 = fmaf(WaT[k * ATT_H + lane + 32], ov, acc1);
    }
    acc0 = fmaxf(acc0, 0.0f) * w2a;
    acc1 = fmaxf(acc1, 0.0f) * w2b;
    float s = acc0 + acc1;
#pragma unroll
    for (int off = 16; off; off >>= 1) s += __shfl_xor_sync(0xffffffffu, s, off);
    if (lane == 0) att[warp] = 1.0f / (1.0f + expf(-(s + bb2)));
}

// ---------------- PDL launch helper ----------------
template <typename F, typename... Args>
static inline void launch_pdl(F kern, dim3 grid, dim3 block, Args... args) {
    cudaLaunchConfig_t cfg = {};
    cfg.gridDim = grid;
    cfg.blockDim = block;
    cfg.dynamicSmemBytes = 0;
    cfg.stream = 0;
    cudaLaunchAttribute attr[1];
    attr[0].id = cudaLaunchAttributeProgrammaticStreamSerialization;
    attr[0].val.programmaticStreamSerializationAllowed = 1;
    cfg.attrs = attr;
    cfg.numAttrs = 1;
    cudaLaunchKernelEx(&cfg, kern, args...);
}

// ---------------- launch ----------------
extern "C" void kernel_launch(void* const* d_in, const int* in_sizes, int n_in,
                              void* d_out, int out_size)
{
    const float* x    = (const float*)d_in[0];
    const int*   ei   = (const int*)d_in[1];     // (2, E) int32: [src | tgt]
    const float* W1   = (const float*)d_in[2];
    const float* b1   = (const float*)d_in[3];
    const float* W2   = (const float*)d_in[4];
    const float* b2   = (const float*)d_in[5];
    const float* Wa1  = (const float*)d_in[6];
    const float* ba1  = (const float*)d_in[7];
    const float* Wa2  = (const float*)d_in[8];
    const float* ba2  = (const float*)d_in[9];

    const int E = in_sizes[1] / 2;
    const int* src = ei;
    const int* tgt = ei + E;

    float* out_ptr = (float*)d_out;                        // (N, 128)
    float* att_ptr = out_ptr + (size_t)NNODES * OUT_D;     // (N, 1)

    float*         h_p;    cudaGetSymbolAddress((void**)&h_p,    g_h);
    float*         z_p;    cudaGetSymbolAddress((void**)&z_p,    g_z);
    float*         z2_p;   cudaGetSymbolAddress((void**)&z2_p,   g_z2);
    __nv_bfloat16* zb_p;   cudaGetSymbolAddress((void**)&zb_p,   g_zb);
    __nv_bfloat16* zb2_p;  cudaGetSymbolAddress((void**)&zb2_p,  g_zb2);
    float*         inv_p;  cudaGetSymbolAddress((void**)&inv_p,  g_inv);
    int*           cnt_p;  cudaGetSymbolAddress((void**)&cnt_p,  g_cnt);
    int*           off_p;  cudaGetSymbolAddress((void**)&off_p,  g_off);
    int*           cur_p;  cudaGetSymbolAddress((void**)&cur_p,  g_cur);
    int*           bsum_p; cudaGetSymbolAddress((void**)&bsum_p, g_bsum);
    int*           bofs_p; cudaGetSymbolAddress((void**)&bofs_p, g_bofs);
    int*           srcs_p; cudaGetSymbolAddress((void**)&srcs_p, g_srcs);
    float*         wat_p;  cudaGetSymbolAddress((void**)&wat_p,  g_WaT);

    // --- fork side stream: CSR build + Wa1 transpose (hides under GEMMs) ---
    cudaStream_t side;
    cudaStreamCreateWithFlags(&side, cudaStreamNonBlocking);
    cudaEvent_t ev_fork, ev_csr;
    cudaEventCreateWithFlags(&ev_fork, cudaEventDisableTiming);
    cudaEventCreateWithFlags(&ev_csr,  cudaEventDisableTiming);

    cudaEventRecord(ev_fork, 0);
    cudaStreamWaitEvent(side, ev_fork, 0);

    transpose_wa1_kernel<<<(OUT_D * ATT_H + 255) / 256, 256, 0, side>>>(Wa1, wat_p);
    count_kernel<<<(E / 4 + 255) / 256, 256, 0, side>>>(tgt, cnt_p, E);
    scan1_kernel<<<SCAN_BLOCKS, SCAN_TPB, 0, side>>>(cnt_p, bsum_p);
    scan2_kernel<<<1, 64, 0, side>>>(bsum_p, bofs_p, off_p);
    scan3_kernel<<<SCAN_BLOCKS, SCAN_TPB, 0, side>>>(cnt_p, bofs_p, off_p, cur_p, inv_p);
    fill_kernel<<<(E / 4 + 255) / 256, 256, 0, side>>>(src, tgt, cur_p, srcs_p, E);
    cudaEventRecord(ev_csr, side);

    // main: h = relu(x @ W1^T + b1)  — first in chain, normal launch
    {
        dim3 grid(HID / GBN, (NNODES + GBM - 1) / GBM);
        gemm_tf32_kernel<<<grid, 256>>>(x, W1, b1, h_p, (__nv_bfloat16*)nullptr,
                                        NNODES, HID, F_IN, 1);
    }
    // main: z = h @ W2^T  (PDL on gemm1)
    {
        dim3 grid(OUT_D / GBN, (NNODES + GBM - 1) / GBM);
        launch_pdl(gemm_tf32_kernel, grid, dim3(256),
                   h_p, (const float*)W2, (const float*)nullptr, z_p, zb_p,
                   NNODES, OUT_D, HID, 0);
    }

    cudaStreamWaitEvent(0, ev_csr, 0);

    // propagation in z-space (PDL chain): z2 = P z ; out = relu(P z2 + b2)
    {
        int gblocks = (NNODES + 3) / 4;   // 4 nodes per block (2 warps/node)
        launch_pdl(gather_combine128_kernel, dim3(gblocks), dim3(256),
                   (const float*)z_p, (const __nv_bfloat16*)zb_p, z2_p, zb2_p,
                   (const float*)nullptr,
                   (const int*)off_p, (const int*)srcs_p, (const float*)inv_p);
        launch_pdl(gather_combine128_kernel, dim3(gblocks), dim3(256),
                   (const float*)z2_p, (const __nv_bfloat16*)zb2_p, out_ptr,
                   (__nv_bfloat16*)nullptr, (const float*)b2,
                   (const int*)off_p, (const int*)srcs_p, (const float*)inv_p);
    }

    // attention (PDL on gather pass 2)
    launch_pdl(attention_kernel, dim3((NNODES * 32 + 255) / 256), dim3(256),
               (const float*)out_ptr, (const float*)wat_p, ba1, Wa2, ba2,
               att_ptr, NNODES);

    cudaEventDestroy(ev_fork);
    cudaEventDestroy(ev_csr);
    cudaStreamDestroy(side);
}

// round 17
// speedup vs baseline: 1.1265x; 1.0131x over previous
#include <cuda_runtime.h>
#include <cuda_bf16.h>
#include <math.h>
#include <stdint.h>

// ---------------- problem constants ----------------
#define NNODES   10000
#define F_IN     384
#define HID      256
#define OUT_D    128
#define ATT_H    64
#define EDGES_MAX 320000

#define SCAN_BLOCKS 40
#define SCAN_TPB    256   // 40*256 = 10240 >= NNODES
#define GCAP 64           // max half-neighbor-list prefetched to smem (deg/2 ~ 16)

// ---------------- scratch (device globals; no allocation allowed) ----------------
__device__ float           g_h  [NNODES * HID];     // relu(x W1^T + b1), 256-wide
__device__ float           g_z  [NNODES * OUT_D];   // h @ W2^T (pre-bias/relu), 128-wide
__device__ float           g_z2 [NNODES * OUT_D];
__device__ __nv_bfloat16   g_zb [NNODES * OUT_D];   // bf16 shadows for neighbor reads
__device__ __nv_bfloat16   g_zb2[NNODES * OUT_D];
__device__ float g_inv[NNODES];
__device__ int   g_cnt[NNODES];          // zero-init; re-zeroed by scan3 each launch
__device__ int   g_off[NNODES + 1];
__device__ int   g_cur[NNODES];
__device__ int   g_bsum[SCAN_BLOCKS];
__device__ int   g_bofs[SCAN_BLOCKS];
__device__ int   g_srcs[EDGES_MAX];
__device__ float g_WaT[OUT_D * ATT_H];   // Wa1 transposed

// ---------------- count in-degree, 4 edges/thread ----------------
__global__ void count_kernel(const int* __restrict__ tgt, int* __restrict__ cnt, int E) {
    int i = (blockIdx.x * blockDim.x + threadIdx.x) * 4;
    if (i + 4 <= E) {
        int t0 = tgt[i], t1 = tgt[i + 1], t2 = tgt[i + 2], t3 = tgt[i + 3];
        atomicAdd(&cnt[t0], 1);
        atomicAdd(&cnt[t1], 1);
        atomicAdd(&cnt[t2], 1);
        atomicAdd(&cnt[t3], 1);
    } else {
        for (; i < E; i++) atomicAdd(&cnt[tgt[i]], 1);
    }
}

// ---------------- scan phase 1 ----------------
__global__ __launch_bounds__(SCAN_TPB) void scan1_kernel(
    const int* __restrict__ cnt, int* __restrict__ bsum)
{
    __shared__ int wsum[SCAN_TPB / 32];
    int idx = blockIdx.x * SCAN_TPB + threadIdx.x;
    int v = (idx < NNODES) ? cnt[idx] : 0;
    int lane = threadIdx.x & 31;
    int warp = threadIdx.x >> 5;
#pragma unroll
    for (int d = 16; d; d >>= 1) v += __shfl_xor_sync(0xffffffffu, v, d);
    if (lane == 0) wsum[warp] = v;
    __syncthreads();
    if (threadIdx.x == 0) {
        int s = 0;
#pragma unroll
        for (int w = 0; w < SCAN_TPB / 32; w++) s += wsum[w];
        bsum[blockIdx.x] = s;
    }
}

// ---------------- scan phase 2 ----------------
__global__ void scan2_kernel(const int* __restrict__ bsum, int* __restrict__ bofs,
                             int* __restrict__ off)
{
    int lane = threadIdx.x;
    int v = (lane < SCAN_BLOCKS) ? bsum[lane] : 0;
    int lane32 = lane & 31;
    int half = lane >> 5;
    int s = v;
#pragma unroll
    for (int d = 1; d < 32; d <<= 1) {
        int t = __shfl_up_sync(0xffffffffu, s, d);
        if (lane32 >= d) s += t;
    }
    __shared__ int w0tot;
    if (lane == 31) w0tot = s;
    __syncthreads();
    int incl = s + (half ? w0tot : 0);
    if (lane < SCAN_BLOCKS) bofs[lane] = incl - v;
    if (lane == SCAN_BLOCKS - 1) off[NNODES] = incl;
}

// ---------------- scan phase 3 ----------------
__global__ __launch_bounds__(SCAN_TPB) void scan3_kernel(
    int* __restrict__ cnt, const int* __restrict__ bofs,
    int* __restrict__ off, int* __restrict__ cur, float* __restrict__ inv)
{
    __shared__ int wsum[SCAN_TPB / 32];
    int idx = blockIdx.x * SCAN_TPB + threadIdx.x;
    int lane = threadIdx.x & 31;
    int warp = threadIdx.x >> 5;
    int v = (idx < NNODES) ? cnt[idx] : 0;

    int s = v;
#pragma unroll
    for (int d = 1; d < 32; d <<= 1) {
        int t = __shfl_up_sync(0xffffffffu, s, d);
        if (lane >= d) s += t;
    }
    if (lane == 31) wsum[warp] = s;
    __syncthreads();
    if (warp == 0) {
        int ws = (lane < SCAN_TPB / 32) ? wsum[lane] : 0;
#pragma unroll
        for (int d = 1; d < SCAN_TPB / 32; d <<= 1) {
            int t = __shfl_up_sync(0xffffffffu, ws, d);
            if (lane >= d) ws += t;
        }
        if (lane < SCAN_TPB / 32) wsum[lane] = ws;
    }
    __syncthreads();
    int excl = s - v + (warp ? wsum[warp - 1] : 0) + bofs[blockIdx.x];
    if (idx < NNODES) {
        off[idx] = excl;
        cur[idx] = excl;
        inv[idx] = 1.0f / ((float)v + 1.0f);
        cnt[idx] = 0;
    }
}

// ---------------- fill CSR buckets ----------------
__global__ void fill_kernel(const int* __restrict__ src, const int* __restrict__ tgt,
                            int* __restrict__ cur, int* __restrict__ srcs, int E)
{
    int i = (blockIdx.x * blockDim.x + threadIdx.x) * 4;
    if (i + 4 <= E) {
        int t0 = tgt[i], t1 = tgt[i + 1], t2 = tgt[i + 2], t3 = tgt[i + 3];
        int s0 = src[i], s1 = src[i + 1], s2 = src[i + 2], s3 = src[i + 3];
        int p0 = atomicAdd(&cur[t0], 1);
        int p1 = atomicAdd(&cur[t1], 1);
        int p2 = atomicAdd(&cur[t2], 1);
        int p3 = atomicAdd(&cur[t3], 1);
        srcs[p0] = s0;
        srcs[p1] = s1;
        srcs[p2] = s2;
        srcs[p3] = s3;
    } else {
        for (; i < E; i++) {
            int p = atomicAdd(&cur[tgt[i]], 1);
            srcs[p] = src[i];
        }
    }
}

// ---------------- 128-wide gather + combine: 2 warps/node, smem idx prefetch ----------------
// CSR (off/srcs/inv) is event-joined BEFORE this kernel launches, so the index prefetch
// runs in the PDL prelude (overlapping predecessor drain); only zin/zbin need the sync.
__device__ __forceinline__ void acc_bf16x4(float4& acc, uint2 p) {
    __nv_bfloat162 lo = *reinterpret_cast<__nv_bfloat162*>(&p.x);
    __nv_bfloat162 hi = *reinterpret_cast<__nv_bfloat162*>(&p.y);
    float2 f0 = __bfloat1622float2(lo);
    float2 f1 = __bfloat1622float2(hi);
    acc.x += f0.x; acc.y += f0.y; acc.z += f1.x; acc.w += f1.y;
}

__global__ __launch_bounds__(256) void gather_combine128_kernel(
    const float* __restrict__ zin, const __nv_bfloat16* __restrict__ zbin,
    float* __restrict__ zout, __nv_bfloat16* __restrict__ zbout,
    const float* __restrict__ b2,        // non-null => final pass: +bias, relu, no shadow
    const int* __restrict__ off, const int* __restrict__ srcs,
    const float* __restrict__ inv)
{
    __shared__ float sacc[4][OUT_D];
    __shared__ int   sidx[8][GCAP];

    const int warp = threadIdx.x >> 5;
    const int nloc = warp >> 1;          // node within block: 0..3
    const int half = warp & 1;           // which half of the neighbor list
    const int lane = threadIdx.x & 31;
    const int c = lane << 2;
    const int node = blockIdx.x * 4 + nloc;

    // ---- PDL prelude: range + index prefetch + inv (all CSR-ready) ----
    int lo = 0, cnt = 0;
    float myinv = 0.0f;
    if (node < NNODES) {
        int beg = __ldg(off + node);
        int end = __ldg(off + node + 1);
        int mid = beg + ((end - beg + 1) >> 1);
        lo  = half ? mid : beg;
        cnt = (half ? end : mid) - lo;
        if (!half) myinv = __ldg(inv + node);
    }
    for (int j = lane; j < cnt && j < GCAP; j += 32)
        sidx[warp][j] = __ldg(srcs + lo + j);

    // wait for predecessor grid (zin/zbin producer)
    cudaGridDependencySynchronize();
    __syncwarp();   // make this warp's sidx writes visible to all its lanes

    float4 acc = make_float4(0.f, 0.f, 0.f, 0.f);
    if (cnt <= GCAP) {
        int i = 0;
        for (; i + 4 <= cnt; i += 4) {
            int s0 = sidx[warp][i];
            int s1 = sidx[warp][i + 1];
            int s2 = sidx[warp][i + 2];
            int s3 = sidx[warp][i + 3];
            uint2 p0 = *reinterpret_cast<const uint2*>(zbin + (size_t)s0 * OUT_D + c);
            uint2 p1 = *reinterpret_cast<const uint2*>(zbin + (size_t)s1 * OUT_D + c);
            uint2 p2 = *reinterpret_cast<const uint2*>(zbin + (size_t)s2 * OUT_D + c);
            uint2 p3 = *reinterpret_cast<const uint2*>(zbin + (size_t)s3 * OUT_D + c);
            acc_bf16x4(acc, p0);
            acc_bf16x4(acc, p1);
            acc_bf16x4(acc, p2);
            acc_bf16x4(acc, p3);
        }
        for (; i < cnt; i++) {
            int s0 = sidx[warp][i];
            uint2 p0 = *reinterpret_cast<const uint2*>(zbin + (size_t)s0 * OUT_D + c);
            acc_bf16x4(acc, p0);
        }
    } else {
        // fallback (cnt > GCAP; statistically absent at deg~32)
        int i = lo, hi = lo + cnt;
        for (; i + 4 <= hi; i += 4) {
            int s0 = __ldg(srcs + i);
            int s1 = __ldg(srcs + i + 1);
            int s2 = __ldg(srcs + i + 2);
            int s3 = __ldg(srcs + i + 3);
            uint2 p0 = *reinterpret_cast<const uint2*>(zbin + (size_t)s0 * OUT_D + c);
            uint2 p1 = *reinterpret_cast<const uint2*>(zbin + (size_t)s1 * OUT_D + c);
            uint2 p2 = *reinterpret_cast<const uint2*>(zbin + (size_t)s2 * OUT_D + c);
            uint2 p3 = *reinterpret_cast<const uint2*>(zbin + (size_t)s3 * OUT_D + c);
            acc_bf16x4(acc, p0);
            acc_bf16x4(acc, p1);
            acc_bf16x4(acc, p2);
            acc_bf16x4(acc, p3);
        }
        for (; i < hi; i++) {
            int s0 = __ldg(srcs + i);
            uint2 p0 = *reinterpret_cast<const uint2*>(zbin + (size_t)s0 * OUT_D + c);
            acc_bf16x4(acc, p0);
        }
    }

    // odd warp deposits its partial; even warp combines after the barrier
    if (half) *reinterpret_cast<float4*>(&sacc[nloc][c]) = acc;
    __syncthreads();
    if (half || node >= NNODES) return;

    float4 part = *reinterpret_cast<const float4*>(&sacc[nloc][c]);
    acc.x += part.x; acc.y += part.y; acc.z += part.z; acc.w += part.w;

    float sc = 0.3f * myinv;
    float4 zv = *reinterpret_cast<const float4*>(zin + (size_t)node * OUT_D + c);
    zv.x = 0.7f * zv.x + sc * acc.x;
    zv.y = 0.7f * zv.y + sc * acc.y;
    zv.z = 0.7f * zv.z + sc * acc.z;
    zv.w = 0.7f * zv.w + sc * acc.w;

    if (b2) {
        float4 bv = *reinterpret_cast<const float4*>(b2 + c);
        zv.x = fmaxf(zv.x + bv.x, 0.f);
        zv.y = fmaxf(zv.y + bv.y, 0.f);
        zv.z = fmaxf(zv.z + bv.z, 0.f);
        zv.w = fmaxf(zv.w + bv.w, 0.f);
        *reinterpret_cast<float4*>(zout + (size_t)node * OUT_D + c) = zv;
    } else {
        *reinterpret_cast<float4*>(zout + (size_t)node * OUT_D + c) = zv;
        uint2 pk;
        __nv_bfloat162 blo = __floats2bfloat162_rn(zv.x, zv.y);
        __nv_bfloat162 bhi = __floats2bfloat162_rn(zv.z, zv.w);
        pk.x = *reinterpret_cast<uint32_t*>(&blo);
        pk.y = *reinterpret_cast<uint32_t*>(&bhi);
        *reinterpret_cast<uint2*>(zbout + (size_t)node * OUT_D + c) = pk;
    }

    cudaTriggerProgrammaticLaunchCompletion();
}

// ---------------- tf32 tensor-core GEMM (double-buffered regs, single-stage smem, PDL) ----------------
#define GBM 128
#define GBN 64
#define GBK 32
#define SKA 36

__device__ __forceinline__ uint32_t f2tf32(float x) {
    uint32_t r;
    asm("cvt.rna.tf32.f32 %0, %1;" : "=r"(r) : "f"(x));
    return r;
}

__device__ __forceinline__ void mma_tf32(float* c, const uint32_t* a, const uint32_t* b) {
    asm volatile(
        "mma.sync.aligned.m16n8k8.row.col.f32.tf32.tf32.f32 "
        "{%0,%1,%2,%3}, {%4,%5,%6,%7}, {%8,%9}, {%0,%1,%2,%3};"
        : "+f"(c[0]), "+f"(c[1]), "+f"(c[2]), "+f"(c[3])
        : "r"(a[0]), "r"(a[1]), "r"(a[2]), "r"(a[3]), "r"(b[0]), "r"(b[1]));
}

__global__ __launch_bounds__(256) void gemm_tf32_kernel(
    const float* __restrict__ A, const float* __restrict__ B,
    const float* __restrict__ bias,          // nullable
    float* __restrict__ C,
    __nv_bfloat16* __restrict__ Cb,          // nullable
    int M, int N, int K, int do_relu)
{
    __shared__ uint32_t As[GBM][SKA];
    __shared__ uint32_t Bs[GBN][SKA];

    const int tid  = threadIdx.x;
    const int lane = tid & 31;
    const int warp = tid >> 5;
    const int wm = warp >> 1;
    const int wn = warp & 1;
    const int g   = lane >> 2;
    const int tig = lane & 3;
    const int m0 = blockIdx.y * GBM;
    const int n0 = blockIdx.x * GBN;

    const int ar = tid >> 3;
    const int ac4 = (tid & 7) << 2;

    cudaGridDependencySynchronize();

    float acc[2][4][4];
#pragma unroll
    for (int mm = 0; mm < 2; mm++)
#pragma unroll
        for (int nn = 0; nn < 4; nn++)
#pragma unroll
            for (int q = 0; q < 4; q++) acc[mm][nn][q] = 0.0f;

    float4 ra[4], rb[2];
#pragma unroll
    for (int it = 0; it < 4; it++) {
        int r = ar + it * 32;
        int gm = m0 + r;
        ra[it] = (gm < M) ? *reinterpret_cast<const float4*>(A + (size_t)gm * K + ac4)
                          : make_float4(0.f, 0.f, 0.f, 0.f);
    }
#pragma unroll
    for (int it = 0; it < 2; it++) {
        int r = ar + it * 32;
        rb[it] = *reinterpret_cast<const float4*>(B + (size_t)(n0 + r) * K + ac4);
    }

    for (int k0 = 0; k0 < K; k0 += GBK) {
#pragma unroll
        for (int it = 0; it < 4; it++) {
            int r = ar + it * 32;
            As[r][ac4 + 0] = f2tf32(ra[it].x);
            As[r][ac4 + 1] = f2tf32(ra[it].y);
            As[r][ac4 + 2] = f2tf32(ra[it].z);
            As[r][ac4 + 3] = f2tf32(ra[it].w);
        }
#pragma unroll
        for (int it = 0; it < 2; it++) {
            int r = ar + it * 32;
            Bs[r][ac4 + 0] = f2tf32(rb[it].x);
            Bs[r][ac4 + 1] = f2tf32(rb[it].y);
            Bs[r][ac4 + 2] = f2tf32(rb[it].z);
            Bs[r][ac4 + 3] = f2tf32(rb[it].w);
        }
        __syncthreads();

        int kn = k0 + GBK;
        if (kn < K) {
#pragma unroll
            for (int it = 0; it < 4; it++) {
                int r = ar + it * 32;
                int gm = m0 + r;
                ra[it] = (gm < M) ? *reinterpret_cast<const float4*>(A + (size_t)gm * K + kn + ac4)
                                  : make_float4(0.f, 0.f, 0.f, 0.f);
            }
#pragma unroll
            for (int it = 0; it < 2; it++) {
                int r = ar + it * 32;
                rb[it] = *reinterpret_cast<const float4*>(B + (size_t)(n0 + r) * K + kn + ac4);
            }
        }

#pragma unroll
        for (int kk = 0; kk < GBK; kk += 8) {
            uint32_t af[2][4];
#pragma unroll
            for (int mm = 0; mm < 2; mm++) {
                int row = wm * 32 + mm * 16 + g;
                af[mm][0] = As[row][kk + tig];
                af[mm][1] = As[row + 8][kk + tig];
                af[mm][2] = As[row][kk + tig + 4];
                af[mm][3] = As[row + 8][kk + tig + 4];
            }
            uint32_t bf[4][2];
#pragma unroll
            for (int nn = 0; nn < 4; nn++) {
                int col = wn * 32 + nn * 8 + g;
                bf[nn][0] = Bs[col][kk + tig];
                bf[nn][1] = Bs[col][kk + tig + 4];
            }
#pragma unroll
            for (int mm = 0; mm < 2; mm++)
#pragma unroll
                for (int nn = 0; nn < 4; nn++)
                    mma_tf32(acc[mm][nn], af[mm], bf[nn]);
        }
        __syncthreads();
    }

#pragma unroll
    for (int mm = 0; mm < 2; mm++) {
        int r0 = m0 + wm * 32 + mm * 16 + g;
#pragma unroll
        for (int nn = 0; nn < 4; nn++) {
            int col = n0 + wn * 32 + nn * 8 + tig * 2;
            float b0 = bias ? bias[col]     : 0.f;
            float b1 = bias ? bias[col + 1] : 0.f;
#pragma unroll
            for (int half = 0; half < 2; half++) {
                int r = r0 + half * 8;
                if (r >= M) continue;
                float v0 = acc[mm][nn][half * 2 + 0] + b0;
                float v1 = acc[mm][nn][half * 2 + 1] + b1;
                if (do_relu) { v0 = fmaxf(v0, 0.f); v1 = fmaxf(v1, 0.f); }
                C[(size_t)r * N + col]     = v0;
                C[(size_t)r * N + col + 1] = v1;
                if (Cb) {
                    __nv_bfloat162 p = __floats2bfloat162_rn(v0, v1);
                    *reinterpret_cast<uint32_t*>(Cb + (size_t)r * N + col) =
                        *reinterpret_cast<uint32_t*>(&p);
                }
            }
        }
    }

    cudaTriggerProgrammaticLaunchCompletion();
}

// ---------------- transpose Wa1 (64x128) -> WaT (128x64) ----------------
__global__ void transpose_wa1_kernel(const float* __restrict__ Wa1, float* __restrict__ WaT) {
    int idx = blockIdx.x * blockDim.x + threadIdx.x;
    if (idx >= OUT_D * ATT_H) return;
    int k = idx / ATT_H;
    int j = idx % ATT_H;
    WaT[idx] = Wa1[j * OUT_D + k];
}

// ---------------- attention: warp per node, shfl-broadcast row (PDL consumer) ----------------
__global__ __launch_bounds__(256) void attention_kernel(
    const float* __restrict__ out, const float* __restrict__ WaT,
    const float* __restrict__ ba1, const float* __restrict__ Wa2,
    const float* __restrict__ ba2, float* __restrict__ att, int N)
{
    int warp = (blockIdx.x * blockDim.x + threadIdx.x) >> 5;
    int lane = threadIdx.x & 31;

    // prelude independent of `out`
    float acc0 = ba1[lane];
    float acc1 = ba1[lane + 32];
    float w2a = Wa2[lane];
    float w2b = Wa2[lane + 32];
    float bb2 = ba2[0];

    cudaGridDependencySynchronize();

    if (warp >= N) return;
    // one LDG.128 per lane loads the whole 128-wide row across the warp
    float4 ov = *reinterpret_cast<const float4*>(out + (size_t)warp * OUT_D + (lane << 2));

#pragma unroll 4
    for (int sl = 0; sl < 32; sl++) {
        float rx = __shfl_sync(0xffffffffu, ov.x, sl);
        float ry = __shfl_sync(0xffffffffu, ov.y, sl);
        float rz = __shfl_sync(0xffffffffu, ov.z, sl);
        float rw = __shfl_sync(0xffffffffu, ov.w, sl);
        int k0 = sl << 2;   // k ascending: same accumulation order as scalar loop
        acc0 = fmaf(WaT[(k0 + 0) * ATT_H + lane],      rx, acc0);
        acc1 = fmaf(WaT[(k0 + 0) * ATT_H + lane + 32], rx, acc1);
        acc0 = fmaf(WaT[(k0 + 1) * ATT_H + lane],      ry, acc0);
        acc1 = fmaf(WaT[(k0 + 1) * ATT_H + lane + 32], ry, acc1);
        acc0 = fmaf(WaT[(k0 + 2) * ATT_H + lane],      rz, acc0);
        acc1 = fmaf(WaT[(k0 + 2) * ATT_H + lane + 32], rz, acc1);
        acc0 = fmaf(WaT[(k0 + 3) * ATT_H + lane],      rw, acc0);
        acc1 = fmaf(WaT[(k0 + 3) * ATT_H + lane + 32], rw, acc1);
    }
    acc0 = fmaxf(acc0, 0.0f) * w2a;
    acc1 = fmaxf(acc1, 0.0f) * w2b;
    float s = acc0 + acc1;
#pragma unroll
    for (int off = 16; off; off >>= 1) s += __shfl_xor_sync(0xffffffffu, s, off);
    if (lane == 0) att[warp] = 1.0f / (1.0f + expf(-(s + bb2)));
}

// ---------------- PDL launch helper ----------------
template <typename F, typename... Args>
static inline void launch_pdl(F kern, dim3 grid, dim3 block, Args... args) {
    cudaLaunchConfig_t cfg = {};
    cfg.gridDim = grid;
    cfg.blockDim = block;
    cfg.dynamicSmemBytes = 0;
    cfg.stream = 0;
    cudaLaunchAttribute attr[1];
    attr[0].id = cudaLaunchAttributeProgrammaticStreamSerialization;
    attr[0].val.programmaticStreamSerializationAllowed = 1;
    cfg.attrs = attr;
    cfg.numAttrs = 1;
    cudaLaunchKernelEx(&cfg, kern, args...);
}

// ---------------- launch ----------------
extern "C" void kernel_launch(void* const* d_in, const int* in_sizes, int n_in,
                              void* d_out, int out_size)
{
    const float* x    = (const float*)d_in[0];
    const int*   ei   = (const int*)d_in[1];     // (2, E) int32: [src | tgt]
    const float* W1   = (const float*)d_in[2];
    const float* b1   = (const float*)d_in[3];
    const float* W2   = (const float*)d_in[4];
    const float* b2   = (const float*)d_in[5];
    const float* Wa1  = (const float*)d_in[6];
    const float* ba1  = (const float*)d_in[7];
    const float* Wa2  = (const float*)d_in[8];
    const float* ba2  = (const float*)d_in[9];

    const int E = in_sizes[1] / 2;
    const int* src = ei;
    const int* tgt = ei + E;

    float* out_ptr = (float*)d_out;                        // (N, 128)
    float* att_ptr = out_ptr + (size_t)NNODES * OUT_D;     // (N, 1)

    float*         h_p;    cudaGetSymbolAddress((void**)&h_p,    g_h);
    float*         z_p;    cudaGetSymbolAddress((void**)&z_p,    g_z);
    float*         z2_p;   cudaGetSymbolAddress((void**)&z2_p,   g_z2);
    __nv_bfloat16* zb_p;   cudaGetSymbolAddress((void**)&zb_p,   g_zb);
    __nv_bfloat16* zb2_p;  cudaGetSymbolAddress((void**)&zb2_p,  g_zb2);
    float*         inv_p;  cudaGetSymbolAddress((void**)&inv_p,  g_inv);
    int*           cnt_p;  cudaGetSymbolAddress((void**)&cnt_p,  g_cnt);
    int*           off_p;  cudaGetSymbolAddress((void**)&off_p,  g_off);
    int*           cur_p;  cudaGetSymbolAddress((void**)&cur_p,  g_cur);
    int*           bsum_p; cudaGetSymbolAddress((void**)&bsum_p, g_bsum);
    int*           bofs_p; cudaGetSymbolAddress((void**)&bofs_p, g_bofs);
    int*           srcs_p; cudaGetSymbolAddress((void**)&srcs_p, g_srcs);
    float*         wat_p;  cudaGetSymbolAddress((void**)&wat_p,  g_WaT);

    // --- fork side stream: CSR build + Wa1 transpose (hides under GEMMs) ---
    cudaStream_t side;
    cudaStreamCreateWithFlags(&side, cudaStreamNonBlocking);
    cudaEvent_t ev_fork, ev_csr;
    cudaEventCreateWithFlags(&ev_fork, cudaEventDisableTiming);
    cudaEventCreateWithFlags(&ev_csr,  cudaEventDisableTiming);

    cudaEventRecord(ev_fork, 0);
    cudaStreamWaitEvent(side, ev_fork, 0);

    transpose_wa1_kernel<<<(OUT_D * ATT_H + 255) / 256, 256, 0, side>>>(Wa1, wat_p);
    count_kernel<<<(E / 4 + 255) / 256, 256, 0, side>>>(tgt, cnt_p, E);
    scan1_kernel<<<SCAN_BLOCKS, SCAN_TPB, 0, side>>>(cnt_p, bsum_p);
    scan2_kernel<<<1, 64, 0, side>>>(bsum_p, bofs_p, off_p);
    scan3_kernel<<<SCAN_BLOCKS, SCAN_TPB, 0, side>>>(cnt_p, bofs_p, off_p, cur_p, inv_p);
    fill_kernel<<<(E / 4 + 255) / 256, 256, 0, side>>>(src, tgt, cur_p, srcs_p, E);
    cudaEventRecord(ev_csr, side);

    // main: h = relu(x @ W1^T + b1)  — first in chain, normal launch
    {
        dim3 grid(HID / GBN, (NNODES + GBM - 1) / GBM);
        gemm_tf32_kernel<<<grid, 256>>>(x, W1, b1, h_p, (__nv_bfloat16*)nullptr,
                                        NNODES, HID, F_IN, 1);
    }
    // main: z = h @ W2^T  (PDL on gemm1)
    {
        dim3 grid(OUT_D / GBN, (NNODES + GBM - 1) / GBM);
        launch_pdl(gemm_tf32_kernel, grid, dim3(256),
                   h_p, (const float*)W2, (const float*)nullptr, z_p, zb_p,
                   NNODES, OUT_D, HID, 0);
    }

    cudaStreamWaitEvent(0, ev_csr, 0);

    // propagation in z-space (PDL chain): z2 = P z ; out = relu(P z2 + b2)
    {
        int gblocks = (NNODES + 3) / 4;   // 4 nodes per block (2 warps/node)
        launch_pdl(gather_combine128_kernel, dim3(gblocks), dim3(256),
                   (const float*)z_p, (const __nv_bfloat16*)zb_p, z2_p, zb2_p,
                   (const float*)nullptr,
                   (const int*)off_p, (const int*)srcs_p, (const float*)inv_p);
        launch_pdl(gather_combine128_kernel, dim3(gblocks), dim3(256),
                   (const float*)z2_p, (const __nv_bfloat16*)zb2_p, out_ptr,
                   (__nv_bfloat16*)nullptr, (const float*)b2,
                   (const int*)off_p, (const int*)srcs_p, (const float*)inv_p);
    }

    // attention (PDL on gather pass 2)
    launch_pdl(attention_kernel, dim3((NNODES * 32 + 255) / 256), dim3(256),
               (const float*)out_ptr, (const float*)wat_p, ba1, Wa2, ba2,
               att_ptr, NNODES);

    cudaEventDestroy(ev_fork);
    cudaEventDestroy(ev_csr);
    cudaStreamDestroy(side);
}